// round 2
// baseline (speedup 1.0000x reference)
#include <cuda_runtime.h>
#include <math.h>

#define NN 49152
#define NE 393216
#define DIM 256
#define EEMB 128
#define DEPTH 4

// ---- scratch (static device globals; no runtime allocation) ----
__device__ float g_e[(size_t)NE * EEMB];   // edge embeddings
__device__ float g_R[(size_t)NE * DIM];    // e @ Wc
__device__ float g_P[(size_t)NN * DIM];    // h @ Wa + b
__device__ float g_Q[(size_t)NN * DIM];    // h @ Wb
__device__ float g_hA[(size_t)NN * DIM];
__device__ float g_hB[(size_t)NN * DIM];
__device__ float g_x[(size_t)NN * DIM];

// buffer ids (host passes small ints; device resolves to global arrays —
// avoids any runtime API calls inside kernel_launch)
#define B_E  0
#define B_R  1
#define B_P  2
#define B_Q  3
#define B_HA 4
#define B_HB 5
#define B_X  6

__device__ __forceinline__ float* bufsel(int id) {
    switch (id) {
        case B_E:  return g_e;
        case B_R:  return g_R;
        case B_P:  return g_P;
        case B_Q:  return g_Q;
        case B_HA: return g_hA;
        case B_HB: return g_hB;
        default:   return g_x;
    }
}

__device__ __forceinline__ float gelu_f(float v) {
    return 0.5f * v * (1.0f + erff(v * 0.70710678118654752440f));
}

// ---------------------------------------------------------------------------
// float4 copy between scratch buffers
// ---------------------------------------------------------------------------
__global__ void copy_k(int sid, int did, int n4) {
    int i = blockIdx.x * blockDim.x + threadIdx.x;
    if (i < n4) ((float4*)bufsel(did))[i] = ((const float4*)bufsel(sid))[i];
}

// final copy scratch -> harness d_out
__global__ void copy_out_k(int sid, float* __restrict__ d, int n4) {
    int i = blockIdx.x * blockDim.x + threadIdx.x;
    if (i < n4) ((float4*)d)[i] = ((const float4*)bufsel(sid))[i];
}

// copy harness input -> scratch
__global__ void copy_in_k(const float* __restrict__ s, int did, int n4) {
    int i = blockIdx.x * blockDim.x + threadIdx.x;
    if (i < n4) ((float4*)bufsel(did))[i] = ((const float4*)s)[i];
}

// ---------------------------------------------------------------------------
// edge embedder: e = gelu(attr @ w1 + b1) @ w2 + b2   -> g_e
// ---------------------------------------------------------------------------
__global__ void __launch_bounds__(256) edge_embed_k(
    const float* __restrict__ attr,
    const float* __restrict__ w1, const float* __restrict__ b1,
    const float* __restrict__ w2, const float* __restrict__ b2)
{
    __shared__ float hid[2][EEMB];
    const int sub = threadIdx.x >> 7;
    const int j   = threadIdx.x & 127;
    const int e   = blockIdx.x * 2 + sub;

    float4 a = *(const float4*)(attr + (size_t)e * 4);
    float t = b1[j] + a.x * w1[j] + a.y * w1[EEMB + j]
                    + a.z * w1[2 * EEMB + j] + a.w * w1[3 * EEMB + j];
    hid[sub][j] = gelu_f(t);
    __syncthreads();

    float o0 = 0.f, o1 = 0.f, o2 = 0.f, o3 = 0.f;
#pragma unroll
    for (int k = 0; k < EEMB; k += 4) {
        o0 += hid[sub][k + 0] * __ldg(w2 + (k + 0) * EEMB + j);
        o1 += hid[sub][k + 1] * __ldg(w2 + (k + 1) * EEMB + j);
        o2 += hid[sub][k + 2] * __ldg(w2 + (k + 2) * EEMB + j);
        o3 += hid[sub][k + 3] * __ldg(w2 + (k + 3) * EEMB + j);
    }
    g_e[(size_t)e * EEMB + j] = b2[j] + ((o0 + o1) + (o2 + o3));
}

// ---------------------------------------------------------------------------
// tiled fp32 GEMM: C[M x 256] = act(A[M x K] @ W[K x 256] + bias) (+ res)
// BM=BN=64, BK=16, 256 threads, 4x4 per-thread tile. M % 64 == 0.
// ACT: 0 = identity, 1 = gelu.  resId < 0 -> no residual.
// ---------------------------------------------------------------------------
template<int ACT>
__global__ void __launch_bounds__(256) gemm_k(
    int Aid, const float* __restrict__ W,
    const float* __restrict__ bias, int resId,
    int Cid, int M, int K)
{
    const float* __restrict__ A = bufsel(Aid);
    float* __restrict__ C = bufsel(Cid);

    __shared__ float As[16][65];
    __shared__ float Bs[16][64];

    const int tid = threadIdx.x;
    const int bm = blockIdx.x * 64;
    const int bn = blockIdx.y * 64;
    const int tm = (tid >> 4) * 4;
    const int tn = (tid & 15) * 4;
    const int ar = tid >> 2;
    const int ak = (tid & 3) * 4;
    const int wr = tid >> 4;
    const int wn = (tid & 15) * 4;

    const float* Ap = A + (size_t)(bm + ar) * K + ak;
    const float* Wp = W + (size_t)wr * DIM + bn + wn;

    float acc[4][4] = {};

    for (int k0 = 0; k0 < K; k0 += 16) {
        float4 av = *(const float4*)(Ap + k0);
        As[ak + 0][ar] = av.x;
        As[ak + 1][ar] = av.y;
        As[ak + 2][ar] = av.z;
        As[ak + 3][ar] = av.w;
        *(float4*)&Bs[wr][wn] = *(const float4*)(Wp + (size_t)k0 * DIM);
        __syncthreads();
#pragma unroll
        for (int k = 0; k < 16; k++) {
            float a0 = As[k][tm + 0];
            float a1 = As[k][tm + 1];
            float a2 = As[k][tm + 2];
            float a3 = As[k][tm + 3];
            float4 b = *(const float4*)&Bs[k][tn];
            acc[0][0] += a0 * b.x; acc[0][1] += a0 * b.y; acc[0][2] += a0 * b.z; acc[0][3] += a0 * b.w;
            acc[1][0] += a1 * b.x; acc[1][1] += a1 * b.y; acc[1][2] += a1 * b.z; acc[1][3] += a1 * b.w;
            acc[2][0] += a2 * b.x; acc[2][1] += a2 * b.y; acc[2][2] += a2 * b.z; acc[2][3] += a2 * b.w;
            acc[3][0] += a3 * b.x; acc[3][1] += a3 * b.y; acc[3][2] += a3 * b.z; acc[3][3] += a3 * b.w;
        }
        __syncthreads();
    }

    float4 bj;
    if (bias) bj = *(const float4*)(bias + bn + tn);
    else      bj = make_float4(0.f, 0.f, 0.f, 0.f);

    const float* res = (resId >= 0) ? bufsel(resId) : nullptr;

#pragma unroll
    for (int i = 0; i < 4; i++) {
        size_t off = (size_t)(bm + tm + i) * DIM + bn + tn;
        float4 v;
        v.x = acc[i][0] + bj.x;
        v.y = acc[i][1] + bj.y;
        v.z = acc[i][2] + bj.z;
        v.w = acc[i][3] + bj.w;
        if (ACT == 1) {
            v.x = gelu_f(v.x); v.y = gelu_f(v.y);
            v.z = gelu_f(v.z); v.w = gelu_f(v.w);
        }
        if (res) {
            float4 r = *(const float4*)(res + off);
            v.x += r.x; v.y += r.y; v.z += r.z; v.w += r.w;
        }
        *(float4*)(C + off) = v;
    }
}

// ---------------------------------------------------------------------------
// scatter: out[dst] += gelu(P[src] + Q[dst] + R[e])   (bias folded into P)
// ---------------------------------------------------------------------------
__global__ void __launch_bounds__(256) scatter_k(
    const int* __restrict__ ei, int outId)
{
    float* __restrict__ out = bufsel(outId);
    int gt = blockIdx.x * 256 + threadIdx.x;
    int e  = gt >> 6;
    int c  = (gt & 63) * 4;
    int s = ei[e];
    int d = ei[NE + e];

    float4 p = *(const float4*)(g_P + (size_t)s * DIM + c);
    float4 q = *(const float4*)(g_Q + (size_t)d * DIM + c);
    float4 r = *(const float4*)(g_R + (size_t)e * DIM + c);
    float4 m;
    m.x = gelu_f(p.x + q.x + r.x);
    m.y = gelu_f(p.y + q.y + r.y);
    m.z = gelu_f(p.z + q.z + r.z);
    m.w = gelu_f(p.w + q.w + r.w);

    float* o = out + (size_t)d * DIM + c;
    asm volatile("red.global.add.v4.f32 [%0], {%1, %2, %3, %4};"
                 :: "l"(o), "f"(m.x), "f"(m.y), "f"(m.z), "f"(m.w)
                 : "memory");
}

// ---------------------------------------------------------------------------
extern "C" void kernel_launch(void* const* d_in, const int* in_sizes, int n_in,
                              void* d_out, int out_size)
{
    const float* x     = (const float*)d_in[0];
    const int*   ei    = (const int*)d_in[1];
    const float* attr  = (const float*)d_in[2];
    const float* ee_w1 = (const float*)d_in[3];
    const float* ee_b1 = (const float*)d_in[4];
    const float* ee_w2 = (const float*)d_in[5];
    const float* ee_b2 = (const float*)d_in[6];
    const float* ff1_w = (const float*)d_in[7];
    const float* ff1_b = (const float*)d_in[8];
    const float* mp1_w = (const float*)d_in[9];
    const float* mp1_b = (const float*)d_in[10];
    const float* mp2_w = (const float*)d_in[11];
    const float* mp2_b = (const float*)d_in[12];
    const float* ff2_w = (const float*)d_in[13];
    const float* ff2_b = (const float*)d_in[14];
    float* out = (float*)d_out;

    const int n4 = NN * DIM / 4;
    const int cb = (n4 + 255) / 256;
    const dim3 gN(NN / 64, 4);
    const dim3 gE(NE / 64, 4);

    copy_in_k<<<cb, 256>>>(x, B_X, n4);
    edge_embed_k<<<NE / 2, 256>>>(attr, ee_w1, ee_b1, ee_w2, ee_b2);

    for (int i = 0; i < DEPTH; i++) {
        const float* f1w = ff1_w + (size_t)i * DIM * DIM;
        const float* f2w = ff2_w + (size_t)i * DIM * DIM;
        const float* m1w = mp1_w + (size_t)i * 640 * DIM;
        const float* m2w = mp2_w + (size_t)i * 640 * DIM;

        // h = gelu(x @ ff1_w + ff1_b)   -> hA
        gemm_k<1><<<gN, 256>>>(B_X, f1w, ff1_b + i * DIM, -1, B_HA, NN, DIM);

        // message pass 1: hA -> hB
        gemm_k<0><<<gN, 256>>>(B_HA, m1w,             mp1_b + i * DIM, -1, B_P, NN, DIM); // Wa + b
        gemm_k<0><<<gN, 256>>>(B_HA, m1w + 256 * DIM, nullptr,         -1, B_Q, NN, DIM); // Wb
        gemm_k<0><<<gE, 256>>>(B_E,  m1w + 512 * DIM, nullptr,         -1, B_R, NE, EEMB);// Wc
        copy_k<<<cb, 256>>>(B_HA, B_HB, n4);
        scatter_k<<<NE / 4, 256>>>(ei, B_HB);

        // message pass 2: hB -> hA
        gemm_k<0><<<gN, 256>>>(B_HB, m2w,             mp2_b + i * DIM, -1, B_P, NN, DIM);
        gemm_k<0><<<gN, 256>>>(B_HB, m2w + 256 * DIM, nullptr,         -1, B_Q, NN, DIM);
        gemm_k<0><<<gE, 256>>>(B_E,  m2w + 512 * DIM, nullptr,         -1, B_R, NE, EEMB);
        copy_k<<<cb, 256>>>(B_HB, B_HA, n4);
        scatter_k<<<NE / 4, 256>>>(ei, B_HA);

        // x = x + hA @ ff2_w + ff2_b
        gemm_k<0><<<gN, 256>>>(B_HA, f2w, ff2_b + i * DIM, B_X, B_X, NN, DIM);
    }

    copy_out_k<<<cb, 256>>>(B_X, out, n4);
}

// round 5
// speedup vs baseline: 1.6950x; 1.6950x over previous
#include <cuda_runtime.h>
#include <math.h>

#define NN 49152
#define NE 393216
#define DIM 256
#define EEMB 128
#define DEPTH 4

// ---- scratch (static device globals; no runtime allocation) ----
__device__ float g_e[(size_t)NE * EEMB];   // edge embeddings
__device__ float g_R[(size_t)NE * DIM];    // e @ Wc
__device__ float g_P[(size_t)NN * DIM];    // h @ Wa + b
__device__ float g_Q[(size_t)NN * DIM];    // h @ Wb
__device__ float g_hA[(size_t)NN * DIM];
__device__ float g_hB[(size_t)NN * DIM];
__device__ float g_x[(size_t)NN * DIM];

#define B_E  0
#define B_R  1
#define B_P  2
#define B_Q  3
#define B_HA 4
#define B_HB 5
#define B_X  6

__device__ __forceinline__ float* bufsel(int id) {
    switch (id) {
        case B_E:  return g_e;
        case B_R:  return g_R;
        case B_P:  return g_P;
        case B_Q:  return g_Q;
        case B_HA: return g_hA;
        case B_HB: return g_hB;
        default:   return g_x;
    }
}

__device__ __forceinline__ float gelu_f(float v) {
    return 0.5f * v * (1.0f + erff(v * 0.70710678118654752440f));
}

__device__ __forceinline__ unsigned tf32r(float f) {
    unsigned u;
    asm("cvt.rna.tf32.f32 %0, %1;" : "=r"(u) : "f"(f));
    return u;
}

__device__ __forceinline__ void mma_tf32(float* c, const unsigned* a, const unsigned* b) {
    asm volatile(
        "mma.sync.aligned.m16n8k8.row.col.f32.tf32.tf32.f32 "
        "{%0,%1,%2,%3}, {%4,%5,%6,%7}, {%8,%9}, {%0,%1,%2,%3};\n"
        : "+f"(c[0]), "+f"(c[1]), "+f"(c[2]), "+f"(c[3])
        : "r"(a[0]), "r"(a[1]), "r"(a[2]), "r"(a[3]), "r"(b[0]), "r"(b[1]));
}

// ---------------------------------------------------------------------------
// copies (proven in R2)
// ---------------------------------------------------------------------------
__global__ void copy_k(int sid, int did, int n4) {
    int i = blockIdx.x * blockDim.x + threadIdx.x;
    if (i < n4) ((float4*)bufsel(did))[i] = ((const float4*)bufsel(sid))[i];
}
__global__ void copy_out_k(int sid, float* __restrict__ d, int n4) {
    int i = blockIdx.x * blockDim.x + threadIdx.x;
    if (i < n4) ((float4*)d)[i] = ((const float4*)bufsel(sid))[i];
}
__global__ void copy_in_k(const float* __restrict__ s, int did, int n4) {
    int i = blockIdx.x * blockDim.x + threadIdx.x;
    if (i < n4) ((float4*)bufsel(did))[i] = ((const float4*)s)[i];
}

// ---------------------------------------------------------------------------
// edge embedder (proven in R2): e = gelu(attr @ w1 + b1) @ w2 + b2 -> g_e
// ---------------------------------------------------------------------------
__global__ void __launch_bounds__(256) edge_embed_k(
    const float* __restrict__ attr,
    const float* __restrict__ w1, const float* __restrict__ b1,
    const float* __restrict__ w2, const float* __restrict__ b2)
{
    __shared__ float hid[2][EEMB];
    const int sub = threadIdx.x >> 7;
    const int j   = threadIdx.x & 127;
    const int e   = blockIdx.x * 2 + sub;

    float4 a = *(const float4*)(attr + (size_t)e * 4);
    float t = b1[j] + a.x * w1[j] + a.y * w1[EEMB + j]
                    + a.z * w1[2 * EEMB + j] + a.w * w1[3 * EEMB + j];
    hid[sub][j] = gelu_f(t);
    __syncthreads();

    float o0 = 0.f, o1 = 0.f, o2 = 0.f, o3 = 0.f;
#pragma unroll
    for (int k = 0; k < EEMB; k += 4) {
        o0 += hid[sub][k + 0] * __ldg(w2 + (k + 0) * EEMB + j);
        o1 += hid[sub][k + 1] * __ldg(w2 + (k + 1) * EEMB + j);
        o2 += hid[sub][k + 2] * __ldg(w2 + (k + 2) * EEMB + j);
        o3 += hid[sub][k + 3] * __ldg(w2 + (k + 3) * EEMB + j);
    }
    g_e[(size_t)e * EEMB + j] = b2[j] + ((o0 + o1) + (o2 + o3));
}

// ---------------------------------------------------------------------------
// tf32 tensor-core GEMM: C[M x 256] = act(A[M x K] @ W[K x 256] + bias)[+res]
//   BM=128, BN=128, BK=16, 256 threads = 8 warps of 64x32 (m16n8k8 mma).
// ---------------------------------------------------------------------------
template<int ACT>
__global__ void __launch_bounds__(256) mma_gemm_k(
    int Aid, const float* __restrict__ W, const float* __restrict__ bias,
    int resId, int Cid, int K)
{
    __shared__ unsigned As[16][136];   // [k][m], pad 8
    __shared__ unsigned Bs[16][136];   // [k][n]

    const float* __restrict__ A = bufsel(Aid);
    float* __restrict__ C = bufsel(Cid);

    const int tid  = threadIdx.x;
    const int bm   = blockIdx.x * 128;
    const int bn   = blockIdx.y * 128;
    const int w    = tid >> 5;
    const int lane = tid & 31;
    const int g    = lane >> 2;     // 0..7
    const int tq   = lane & 3;      // 0..3
    const int wm   = (w & 1) * 64;  // 2 warps along M
    const int wn   = (w >> 1) * 32; // 4 warps along N

    // loader mapping: A rows by tid&127, 8 k-values each; B rows by tid>>5
    const int ar  = tid & 127;
    const int ak0 = (tid >> 7);      // 0..1 (k-quads 0/1 then 2/3)
    const int bk0 = tid >> 5;        // 0..7
    const int bq  = (tid & 31) * 4;  // 0..124

    const float* Ag  = A + (size_t)(bm + ar) * K;
    const float* Wg0 = W + (size_t)bk0 * DIM + bn + bq;
    const float* Wg1 = W + (size_t)(bk0 + 8) * DIM + bn + bq;

    float acc[4][4][4];
#pragma unroll
    for (int mi = 0; mi < 4; mi++)
#pragma unroll
        for (int ni = 0; ni < 4; ni++)
#pragma unroll
            for (int r = 0; r < 4; r++) acc[mi][ni][r] = 0.f;

    for (int k0 = 0; k0 < K; k0 += 16) {
        float4 av0 = *(const float4*)(Ag + k0 + ak0 * 4);
        float4 av1 = *(const float4*)(Ag + k0 + (ak0 + 2) * 4);
        float4 bv0 = *(const float4*)(Wg0 + (size_t)k0 * DIM);
        float4 bv1 = *(const float4*)(Wg1 + (size_t)k0 * DIM);

        As[ak0 * 4 + 0][ar] = tf32r(av0.x);
        As[ak0 * 4 + 1][ar] = tf32r(av0.y);
        As[ak0 * 4 + 2][ar] = tf32r(av0.z);
        As[ak0 * 4 + 3][ar] = tf32r(av0.w);
        As[(ak0 + 2) * 4 + 0][ar] = tf32r(av1.x);
        As[(ak0 + 2) * 4 + 1][ar] = tf32r(av1.y);
        As[(ak0 + 2) * 4 + 2][ar] = tf32r(av1.z);
        As[(ak0 + 2) * 4 + 3][ar] = tf32r(av1.w);

        Bs[bk0][bq + 0] = tf32r(bv0.x);
        Bs[bk0][bq + 1] = tf32r(bv0.y);
        Bs[bk0][bq + 2] = tf32r(bv0.z);
        Bs[bk0][bq + 3] = tf32r(bv0.w);
        Bs[bk0 + 8][bq + 0] = tf32r(bv1.x);
        Bs[bk0 + 8][bq + 1] = tf32r(bv1.y);
        Bs[bk0 + 8][bq + 2] = tf32r(bv1.z);
        Bs[bk0 + 8][bq + 3] = tf32r(bv1.w);
        __syncthreads();

#pragma unroll
        for (int ks = 0; ks < 2; ks++) {
            const int kb = ks * 8;
            unsigned a[4][4], b[4][2];
#pragma unroll
            for (int mi = 0; mi < 4; mi++) {
                const int m0 = wm + mi * 16 + g;
                a[mi][0] = As[kb + tq][m0];
                a[mi][1] = As[kb + tq][m0 + 8];
                a[mi][2] = As[kb + tq + 4][m0];
                a[mi][3] = As[kb + tq + 4][m0 + 8];
            }
#pragma unroll
            for (int ni = 0; ni < 4; ni++) {
                const int n0 = wn + ni * 8 + g;
                b[ni][0] = Bs[kb + tq][n0];
                b[ni][1] = Bs[kb + tq + 4][n0];
            }
#pragma unroll
            for (int mi = 0; mi < 4; mi++)
#pragma unroll
                for (int ni = 0; ni < 4; ni++)
                    mma_tf32(acc[mi][ni], a[mi], b[ni]);
        }
        __syncthreads();
    }

    const float* res = (resId >= 0) ? bufsel(resId) : nullptr;
#pragma unroll
    for (int mi = 0; mi < 4; mi++) {
#pragma unroll
        for (int h = 0; h < 2; h++) {
            const int row = bm + wm + mi * 16 + g + h * 8;
#pragma unroll
            for (int ni = 0; ni < 4; ni++) {
                const int c = bn + wn + ni * 8 + tq * 2;
                float v0 = acc[mi][ni][h * 2 + 0];
                float v1 = acc[mi][ni][h * 2 + 1];
                if (bias) {
                    float2 bb = *(const float2*)(bias + c);
                    v0 += bb.x; v1 += bb.y;
                }
                if (ACT == 1) { v0 = gelu_f(v0); v1 = gelu_f(v1); }
                const size_t off = (size_t)row * DIM + c;
                if (res) {
                    float2 r = *(const float2*)(res + off);
                    v0 += r.x; v1 += r.y;
                }
                float2 o; o.x = v0; o.y = v1;
                *(float2*)(C + off) = o;
            }
        }
    }
}

// ---------------------------------------------------------------------------
// scatter (proven in R2): out[dst] += gelu(P[src] + Q[dst] + R[e])
// ---------------------------------------------------------------------------
__global__ void __launch_bounds__(256) scatter_k(
    const int* __restrict__ ei, int outId)
{
    float* __restrict__ out = bufsel(outId);
    int gt = blockIdx.x * 256 + threadIdx.x;
    int e  = gt >> 6;
    int c  = (gt & 63) * 4;
    int s = ei[e];
    int d = ei[NE + e];

    float4 p = *(const float4*)(g_P + (size_t)s * DIM + c);
    float4 q = *(const float4*)(g_Q + (size_t)d * DIM + c);
    float4 r = *(const float4*)(g_R + (size_t)e * DIM + c);
    float4 m;
    m.x = gelu_f(p.x + q.x + r.x);
    m.y = gelu_f(p.y + q.y + r.y);
    m.z = gelu_f(p.z + q.z + r.z);
    m.w = gelu_f(p.w + q.w + r.w);

    float* o = out + (size_t)d * DIM + c;
    asm volatile("red.global.add.v4.f32 [%0], {%1, %2, %3, %4};"
                 :: "l"(o), "f"(m.x), "f"(m.y), "f"(m.z), "f"(m.w)
                 : "memory");
}

// ---------------------------------------------------------------------------
extern "C" void kernel_launch(void* const* d_in, const int* in_sizes, int n_in,
                              void* d_out, int out_size)
{
    const float* x     = (const float*)d_in[0];
    const int*   ei    = (const int*)d_in[1];
    const float* attr  = (const float*)d_in[2];
    const float* ee_w1 = (const float*)d_in[3];
    const float* ee_b1 = (const float*)d_in[4];
    const float* ee_w2 = (const float*)d_in[5];
    const float* ee_b2 = (const float*)d_in[6];
    const float* ff1_w = (const float*)d_in[7];
    const float* ff1_b = (const float*)d_in[8];
    const float* mp1_w = (const float*)d_in[9];
    const float* mp1_b = (const float*)d_in[10];
    const float* mp2_w = (const float*)d_in[11];
    const float* mp2_b = (const float*)d_in[12];
    const float* ff2_w = (const float*)d_in[13];
    const float* ff2_b = (const float*)d_in[14];
    float* out = (float*)d_out;

    const int n4 = NN * DIM / 4;
    const int cb = (n4 + 255) / 256;
    const dim3 gN(NN / 128, 2);     // node GEMMs: M=49152
    const dim3 gE(NE / 128, 2);     // edge GEMM: M=393216

    copy_in_k<<<cb, 256>>>(x, B_X, n4);
    edge_embed_k<<<NE / 2, 256>>>(attr, ee_w1, ee_b1, ee_w2, ee_b2);

    for (int i = 0; i < DEPTH; i++) {
        const float* f1w = ff1_w + (size_t)i * DIM * DIM;
        const float* f2w = ff2_w + (size_t)i * DIM * DIM;
        const float* m1w = mp1_w + (size_t)i * 640 * DIM;
        const float* m2w = mp2_w + (size_t)i * 640 * DIM;

        // h = gelu(x @ ff1_w + ff1_b) -> hA
        mma_gemm_k<1><<<gN, 256>>>(B_X, f1w, ff1_b + i * DIM, -1, B_HA, DIM);

        // message pass 1: hA -> hB
        mma_gemm_k<0><<<gN, 256>>>(B_HA, m1w,             mp1_b + i * DIM, -1, B_P, DIM);
        mma_gemm_k<0><<<gN, 256>>>(B_HA, m1w + 256 * DIM, nullptr,         -1, B_Q, DIM);
        mma_gemm_k<0><<<gE, 256>>>(B_E,  m1w + 512 * DIM, nullptr,         -1, B_R, EEMB);
        copy_k<<<cb, 256>>>(B_HA, B_HB, n4);
        scatter_k<<<NE / 4, 256>>>(ei, B_HB);

        // message pass 2: hB -> hA
        mma_gemm_k<0><<<gN, 256>>>(B_HB, m2w,             mp2_b + i * DIM, -1, B_P, DIM);
        mma_gemm_k<0><<<gN, 256>>>(B_HB, m2w + 256 * DIM, nullptr,         -1, B_Q, DIM);
        mma_gemm_k<0><<<gE, 256>>>(B_E,  m2w + 512 * DIM, nullptr,         -1, B_R, EEMB);
        copy_k<<<cb, 256>>>(B_HB, B_HA, n4);
        scatter_k<<<NE / 4, 256>>>(ei, B_HA);

        // x = x + hA @ ff2_w + ff2_b
        mma_gemm_k<0><<<gN, 256>>>(B_HA, f2w, ff2_b + i * DIM, B_X, B_X, DIM);
    }

    copy_out_k<<<cb, 256>>>(B_X, out, n4);
}

// round 6
// speedup vs baseline: 1.7217x; 1.0157x over previous
#include <cuda_runtime.h>
#include <math.h>

#define NN 49152
#define NE 393216
#define DIM 256
#define EEMB 128
#define DEPTH 4

// ---- scratch (static device globals; no runtime allocation) ----
__device__ float g_e[(size_t)NE * EEMB];   // edge embeddings
__device__ float g_R[(size_t)NE * DIM];    // e @ Wc
__device__ float g_P[(size_t)NN * DIM];    // h @ Wa + b
__device__ float g_Q[(size_t)NN * DIM];    // h @ Wb
__device__ float g_hA[(size_t)NN * DIM];
__device__ float g_hB[(size_t)NN * DIM];
__device__ float g_x[(size_t)NN * DIM];

#define B_E  0
#define B_R  1
#define B_P  2
#define B_Q  3
#define B_HA 4
#define B_HB 5
#define B_X  6

__device__ __forceinline__ float* bufsel(int id) {
    switch (id) {
        case B_E:  return g_e;
        case B_R:  return g_R;
        case B_P:  return g_P;
        case B_Q:  return g_Q;
        case B_HA: return g_hA;
        case B_HB: return g_hB;
        default:   return g_x;
    }
}

__device__ __forceinline__ float gelu_f(float v) {
    return 0.5f * v * (1.0f + erff(v * 0.70710678118654752440f));
}

__device__ __forceinline__ unsigned tf32r(float f) {
    unsigned u;
    asm("cvt.rna.tf32.f32 %0, %1;" : "=r"(u) : "f"(f));
    return u;
}

__device__ __forceinline__ void mma_tf32(float* c, const unsigned* a, const unsigned* b) {
    asm volatile(
        "mma.sync.aligned.m16n8k8.row.col.f32.tf32.tf32.f32 "
        "{%0,%1,%2,%3}, {%4,%5,%6,%7}, {%8,%9}, {%0,%1,%2,%3};\n"
        : "+f"(c[0]), "+f"(c[1]), "+f"(c[2]), "+f"(c[3])
        : "r"(a[0]), "r"(a[1]), "r"(a[2]), "r"(a[3]), "r"(b[0]), "r"(b[1]));
}

// ---------------------------------------------------------------------------
// copies (proven)
// ---------------------------------------------------------------------------
__global__ void copy_k(int sid, int did, int n4) {
    int i = blockIdx.x * blockDim.x + threadIdx.x;
    if (i < n4) ((float4*)bufsel(did))[i] = ((const float4*)bufsel(sid))[i];
}
__global__ void copy_out_k(int sid, float* __restrict__ d, int n4) {
    int i = blockIdx.x * blockDim.x + threadIdx.x;
    if (i < n4) ((float4*)d)[i] = ((const float4*)bufsel(sid))[i];
}
__global__ void copy_in_k(const float* __restrict__ s, int did, int n4) {
    int i = blockIdx.x * blockDim.x + threadIdx.x;
    if (i < n4) ((float4*)bufsel(did))[i] = ((const float4*)s)[i];
}

// ---------------------------------------------------------------------------
// edge embedder (proven): e = gelu(attr @ w1 + b1) @ w2 + b2 -> g_e
// ---------------------------------------------------------------------------
__global__ void __launch_bounds__(256) edge_embed_k(
    const float* __restrict__ attr,
    const float* __restrict__ w1, const float* __restrict__ b1,
    const float* __restrict__ w2, const float* __restrict__ b2)
{
    __shared__ float hid[2][EEMB];
    const int sub = threadIdx.x >> 7;
    const int j   = threadIdx.x & 127;
    const int e   = blockIdx.x * 2 + sub;

    float4 a = *(const float4*)(attr + (size_t)e * 4);
    float t = b1[j] + a.x * w1[j] + a.y * w1[EEMB + j]
                    + a.z * w1[2 * EEMB + j] + a.w * w1[3 * EEMB + j];
    hid[sub][j] = gelu_f(t);
    __syncthreads();

    float o0 = 0.f, o1 = 0.f, o2 = 0.f, o3 = 0.f;
#pragma unroll
    for (int k = 0; k < EEMB; k += 4) {
        o0 += hid[sub][k + 0] * __ldg(w2 + (k + 0) * EEMB + j);
        o1 += hid[sub][k + 1] * __ldg(w2 + (k + 1) * EEMB + j);
        o2 += hid[sub][k + 2] * __ldg(w2 + (k + 2) * EEMB + j);
        o3 += hid[sub][k + 3] * __ldg(w2 + (k + 3) * EEMB + j);
    }
    g_e[(size_t)e * EEMB + j] = b2[j] + ((o0 + o1) + (o2 + o3));
}

// ---------------------------------------------------------------------------
// tf32 tensor-core GEMM: C[M x 256] = act(A[M x K] @ W[K x 256] + bias)[+res]
//   BM=128, BN=128, BK=16, 256 threads = 8 warps of 64x32 (m16n8k8 mma).
//   Register-prefetch pipeline: next tile's global loads issued before the
//   compute loop consumes the current SMEM tile.
// ---------------------------------------------------------------------------
template<int ACT>
__global__ void __launch_bounds__(256, 2) mma_gemm_k(
    int Aid, const float* __restrict__ W, const float* __restrict__ bias,
    int resId, int Cid, int K)
{
    __shared__ unsigned As[16][136];   // [k][m], pad 8
    __shared__ unsigned Bs[16][136];   // [k][n]

    const float* __restrict__ A = bufsel(Aid);
    float* __restrict__ C = bufsel(Cid);

    const int tid  = threadIdx.x;
    const int bm   = blockIdx.x * 128;
    const int bn   = blockIdx.y * 128;
    const int w    = tid >> 5;
    const int lane = tid & 31;
    const int g    = lane >> 2;     // 0..7
    const int tq   = lane & 3;      // 0..3
    const int wm   = (w & 1) * 64;  // 2 warps along M
    const int wn   = (w >> 1) * 32; // 4 warps along N

    // loader mapping: A rows by tid&127, 8 k-values each; B rows by tid>>5
    const int ar  = tid & 127;
    const int ak0 = (tid >> 7);      // 0..1 (k-quads 0/1 then 2/3)
    const int bk0 = tid >> 5;        // 0..7
    const int bq  = (tid & 31) * 4;  // 0..124

    const float* Ag  = A + (size_t)(bm + ar) * K;
    const float* Wg0 = W + (size_t)bk0 * DIM + bn + bq;
    const float* Wg1 = W + (size_t)(bk0 + 8) * DIM + bn + bq;

    float acc[4][4][4];
#pragma unroll
    for (int mi = 0; mi < 4; mi++)
#pragma unroll
        for (int ni = 0; ni < 4; ni++)
#pragma unroll
            for (int r = 0; r < 4; r++) acc[mi][ni][r] = 0.f;

    // prologue: load first tile into registers
    float4 av0 = *(const float4*)(Ag + ak0 * 4);
    float4 av1 = *(const float4*)(Ag + (ak0 + 2) * 4);
    float4 bv0 = *(const float4*)(Wg0);
    float4 bv1 = *(const float4*)(Wg1);

    for (int k0 = 0; k0 < K; k0 += 16) {
        // store current tile into SMEM (tf32-converted)
        As[ak0 * 4 + 0][ar] = tf32r(av0.x);
        As[ak0 * 4 + 1][ar] = tf32r(av0.y);
        As[ak0 * 4 + 2][ar] = tf32r(av0.z);
        As[ak0 * 4 + 3][ar] = tf32r(av0.w);
        As[(ak0 + 2) * 4 + 0][ar] = tf32r(av1.x);
        As[(ak0 + 2) * 4 + 1][ar] = tf32r(av1.y);
        As[(ak0 + 2) * 4 + 2][ar] = tf32r(av1.z);
        As[(ak0 + 2) * 4 + 3][ar] = tf32r(av1.w);

        Bs[bk0][bq + 0] = tf32r(bv0.x);
        Bs[bk0][bq + 1] = tf32r(bv0.y);
        Bs[bk0][bq + 2] = tf32r(bv0.z);
        Bs[bk0][bq + 3] = tf32r(bv0.w);
        Bs[bk0 + 8][bq + 0] = tf32r(bv1.x);
        Bs[bk0 + 8][bq + 1] = tf32r(bv1.y);
        Bs[bk0 + 8][bq + 2] = tf32r(bv1.z);
        Bs[bk0 + 8][bq + 3] = tf32r(bv1.w);
        __syncthreads();

        // prefetch next tile (latency overlapped with compute below)
        if (k0 + 16 < K) {
            av0 = *(const float4*)(Ag + k0 + 16 + ak0 * 4);
            av1 = *(const float4*)(Ag + k0 + 16 + (ak0 + 2) * 4);
            bv0 = *(const float4*)(Wg0 + (size_t)(k0 + 16) * DIM);
            bv1 = *(const float4*)(Wg1 + (size_t)(k0 + 16) * DIM);
        }

#pragma unroll
        for (int ks = 0; ks < 2; ks++) {
            const int kb = ks * 8;
            unsigned a[4][4], b[4][2];
#pragma unroll
            for (int mi = 0; mi < 4; mi++) {
                const int m0 = wm + mi * 16 + g;
                a[mi][0] = As[kb + tq][m0];
                a[mi][1] = As[kb + tq][m0 + 8];
                a[mi][2] = As[kb + tq + 4][m0];
                a[mi][3] = As[kb + tq + 4][m0 + 8];
            }
#pragma unroll
            for (int ni = 0; ni < 4; ni++) {
                const int n0 = wn + ni * 8 + g;
                b[ni][0] = Bs[kb + tq][n0];
                b[ni][1] = Bs[kb + tq + 4][n0];
            }
#pragma unroll
            for (int mi = 0; mi < 4; mi++)
#pragma unroll
                for (int ni = 0; ni < 4; ni++)
                    mma_tf32(acc[mi][ni], a[mi], b[ni]);
        }
        __syncthreads();
    }

    const float* res = (resId >= 0) ? bufsel(resId) : nullptr;
#pragma unroll
    for (int mi = 0; mi < 4; mi++) {
#pragma unroll
        for (int h = 0; h < 2; h++) {
            const int row = bm + wm + mi * 16 + g + h * 8;
#pragma unroll
            for (int ni = 0; ni < 4; ni++) {
                const int c = bn + wn + ni * 8 + tq * 2;
                float v0 = acc[mi][ni][h * 2 + 0];
                float v1 = acc[mi][ni][h * 2 + 1];
                if (bias) {
                    float2 bb = *(const float2*)(bias + c);
                    v0 += bb.x; v1 += bb.y;
                }
                if (ACT == 1) { v0 = gelu_f(v0); v1 = gelu_f(v1); }
                const size_t off = (size_t)row * DIM + c;
                if (res) {
                    float2 r = *(const float2*)(res + off);
                    v0 += r.x; v1 += r.y;
                }
                float2 o; o.x = v0; o.y = v1;
                *(float2*)(C + off) = o;
            }
        }
    }
}

// ---------------------------------------------------------------------------
// scatter (proven): out[dst] += gelu(P[src] + Q[dst] + R[e])
// ---------------------------------------------------------------------------
__global__ void __launch_bounds__(256) scatter_k(
    const int* __restrict__ ei, int outId)
{
    float* __restrict__ out = bufsel(outId);
    int gt = blockIdx.x * 256 + threadIdx.x;
    int e  = gt >> 6;
    int c  = (gt & 63) * 4;
    int s = ei[e];
    int d = ei[NE + e];

    float4 p = *(const float4*)(g_P + (size_t)s * DIM + c);
    float4 q = *(const float4*)(g_Q + (size_t)d * DIM + c);
    float4 r = *(const float4*)(g_R + (size_t)e * DIM + c);
    float4 m;
    m.x = gelu_f(p.x + q.x + r.x);
    m.y = gelu_f(p.y + q.y + r.y);
    m.z = gelu_f(p.z + q.z + r.z);
    m.w = gelu_f(p.w + q.w + r.w);

    float* o = out + (size_t)d * DIM + c;
    asm volatile("red.global.add.v4.f32 [%0], {%1, %2, %3, %4};"
                 :: "l"(o), "f"(m.x), "f"(m.y), "f"(m.z), "f"(m.w)
                 : "memory");
}

// ---------------------------------------------------------------------------
extern "C" void kernel_launch(void* const* d_in, const int* in_sizes, int n_in,
                              void* d_out, int out_size)
{
    const float* x     = (const float*)d_in[0];
    const int*   ei    = (const int*)d_in[1];
    const float* attr  = (const float*)d_in[2];
    const float* ee_w1 = (const float*)d_in[3];
    const float* ee_b1 = (const float*)d_in[4];
    const float* ee_w2 = (const float*)d_in[5];
    const float* ee_b2 = (const float*)d_in[6];
    const float* ff1_w = (const float*)d_in[7];
    const float* ff1_b = (const float*)d_in[8];
    const float* mp1_w = (const float*)d_in[9];
    const float* mp1_b = (const float*)d_in[10];
    const float* mp2_w = (const float*)d_in[11];
    const float* mp2_b = (const float*)d_in[12];
    const float* ff2_w = (const float*)d_in[13];
    const float* ff2_b = (const float*)d_in[14];
    float* out = (float*)d_out;

    const int n4 = NN * DIM / 4;
    const int cb = (n4 + 255) / 256;
    const dim3 gN(NN / 128, 2);     // node GEMMs: M=49152
    const dim3 gE(NE / 128, 2);     // edge GEMM: M=393216

    copy_in_k<<<cb, 256>>>(x, B_X, n4);
    edge_embed_k<<<NE / 2, 256>>>(attr, ee_w1, ee_b1, ee_w2, ee_b2);

    for (int i = 0; i < DEPTH; i++) {
        const float* f1w = ff1_w + (size_t)i * DIM * DIM;
        const float* f2w = ff2_w + (size_t)i * DIM * DIM;
        const float* m1w = mp1_w + (size_t)i * 640 * DIM;
        const float* m2w = mp2_w + (size_t)i * 640 * DIM;

        // h = gelu(x @ ff1_w + ff1_b) -> hA
        mma_gemm_k<1><<<gN, 256>>>(B_X, f1w, ff1_b + i * DIM, -1, B_HA, DIM);

        // message pass 1: hA -> hB
        mma_gemm_k<0><<<gN, 256>>>(B_HA, m1w,             mp1_b + i * DIM, -1, B_P, DIM);
        mma_gemm_k<0><<<gN, 256>>>(B_HA, m1w + 256 * DIM, nullptr,         -1, B_Q, DIM);
        mma_gemm_k<0><<<gE, 256>>>(B_E,  m1w + 512 * DIM, nullptr,         -1, B_R, EEMB);
        copy_k<<<cb, 256>>>(B_HA, B_HB, n4);
        scatter_k<<<NE / 4, 256>>>(ei, B_HB);

        // message pass 2: hB -> hA
        mma_gemm_k<0><<<gN, 256>>>(B_HB, m2w,             mp2_b + i * DIM, -1, B_P, DIM);
        mma_gemm_k<0><<<gN, 256>>>(B_HB, m2w + 256 * DIM, nullptr,         -1, B_Q, DIM);
        mma_gemm_k<0><<<gE, 256>>>(B_E,  m2w + 512 * DIM, nullptr,         -1, B_R, EEMB);
        copy_k<<<cb, 256>>>(B_HB, B_HA, n4);
        scatter_k<<<NE / 4, 256>>>(ei, B_HA);

        // x = x + hA @ ff2_w + ff2_b
        mma_gemm_k<0><<<gN, 256>>>(B_HA, f2w, ff2_b + i * DIM, B_X, B_X, DIM);
    }

    copy_out_k<<<cb, 256>>>(B_X, out, n4);
}

// round 8
// speedup vs baseline: 1.8461x; 1.0723x over previous
#include <cuda_runtime.h>
#include <math.h>

#define NN 49152
#define NE 393216
#define DIM 256
#define EEMB 128
#define DEPTH 4

// ---- scratch (static device globals; no runtime allocation) ----
__device__ float g_e[(size_t)NE * EEMB];   // edge embeddings
__device__ float g_R[(size_t)NE * DIM];    // e @ Wc
__device__ float g_P[(size_t)NN * DIM];    // h @ Wa + b
__device__ float g_Q[(size_t)NN * DIM];    // h @ Wb
__device__ float g_hA[(size_t)NN * DIM];
__device__ float g_hB[(size_t)NN * DIM];
__device__ float g_x[(size_t)NN * DIM];
__device__ float g_wt[1835008];            // tf32-pre-rounded weights

// weight offsets inside g_wt (floats)
#define WOFF_FF1 0
#define WOFF_MP1 262144
#define WOFF_MP2 917504
#define WOFF_FF2 1572864

#define B_E  0
#define B_R  1
#define B_P  2
#define B_Q  3
#define B_HA 4
#define B_HB 5
#define B_X  6

__device__ __forceinline__ float* bufsel(int id) {
    switch (id) {
        case B_E:  return g_e;
        case B_R:  return g_R;
        case B_P:  return g_P;
        case B_Q:  return g_Q;
        case B_HA: return g_hA;
        case B_HB: return g_hB;
        default:   return g_x;
    }
}

__device__ __forceinline__ float gelu_f(float v) {
    return 0.5f * v * (1.0f + erff(v * 0.70710678118654752440f));
}

__device__ __forceinline__ unsigned tf32r(float f) {
    unsigned u;
    asm("cvt.rna.tf32.f32 %0, %1;" : "=r"(u) : "f"(f));
    return u;
}

__device__ __forceinline__ void mma_tf32(float* c, const unsigned* a, const unsigned* b) {
    asm volatile(
        "mma.sync.aligned.m16n8k8.row.col.f32.tf32.tf32.f32 "
        "{%0,%1,%2,%3}, {%4,%5,%6,%7}, {%8,%9}, {%0,%1,%2,%3};\n"
        : "+f"(c[0]), "+f"(c[1]), "+f"(c[2]), "+f"(c[3])
        : "r"(a[0]), "r"(a[1]), "r"(a[2]), "r"(a[3]), "r"(b[0]), "r"(b[1]));
}

__device__ __forceinline__ void cp16(unsigned dst, const void* src) {
    asm volatile("cp.async.cg.shared.global [%0], [%1], 16;"
                 :: "r"(dst), "l"(src));
}

// ---------------------------------------------------------------------------
// weight pre-rounding: g_wt[dstOff4 + i] = rna_tf32(src[i])   (float4 lanes)
// ---------------------------------------------------------------------------
__global__ void cvtw_k(const float* __restrict__ src, int dstOff4, int n4) {
    int i = blockIdx.x * blockDim.x + threadIdx.x;
    if (i < n4) {
        float4 v = ((const float4*)src)[i];
        float4 o;
        o.x = __uint_as_float(tf32r(v.x));
        o.y = __uint_as_float(tf32r(v.y));
        o.z = __uint_as_float(tf32r(v.z));
        o.w = __uint_as_float(tf32r(v.w));
        ((float4*)g_wt)[dstOff4 + i] = o;
    }
}

// ---------------------------------------------------------------------------
// copies (proven)
// ---------------------------------------------------------------------------
__global__ void copy_k(int sid, int did, int n4) {
    int i = blockIdx.x * blockDim.x + threadIdx.x;
    if (i < n4) ((float4*)bufsel(did))[i] = ((const float4*)bufsel(sid))[i];
}
__global__ void copy_out_k(int sid, float* __restrict__ d, int n4) {
    int i = blockIdx.x * blockDim.x + threadIdx.x;
    if (i < n4) ((float4*)d)[i] = ((const float4*)bufsel(sid))[i];
}
__global__ void copy_in_k(const float* __restrict__ s, int did, int n4) {
    int i = blockIdx.x * blockDim.x + threadIdx.x;
    if (i < n4) ((float4*)bufsel(did))[i] = ((const float4*)s)[i];
}

// ---------------------------------------------------------------------------
// edge embedder (proven): e = gelu(attr @ w1 + b1) @ w2 + b2 -> g_e
// ---------------------------------------------------------------------------
__global__ void __launch_bounds__(256) edge_embed_k(
    const float* __restrict__ attr,
    const float* __restrict__ w1, const float* __restrict__ b1,
    const float* __restrict__ w2, const float* __restrict__ b2)
{
    __shared__ float hid[2][EEMB];
    const int sub = threadIdx.x >> 7;
    const int j   = threadIdx.x & 127;
    const int e   = blockIdx.x * 2 + sub;

    float4 a = *(const float4*)(attr + (size_t)e * 4);
    float t = b1[j] + a.x * w1[j] + a.y * w1[EEMB + j]
                    + a.z * w1[2 * EEMB + j] + a.w * w1[3 * EEMB + j];
    hid[sub][j] = gelu_f(t);
    __syncthreads();

    float o0 = 0.f, o1 = 0.f, o2 = 0.f, o3 = 0.f;
#pragma unroll
    for (int k = 0; k < EEMB; k += 4) {
        o0 += hid[sub][k + 0] * __ldg(w2 + (k + 0) * EEMB + j);
        o1 += hid[sub][k + 1] * __ldg(w2 + (k + 1) * EEMB + j);
        o2 += hid[sub][k + 2] * __ldg(w2 + (k + 2) * EEMB + j);
        o3 += hid[sub][k + 3] * __ldg(w2 + (k + 3) * EEMB + j);
    }
    g_e[(size_t)e * EEMB + j] = b2[j] + ((o0 + o1) + (o2 + o3));
}

// ---------------------------------------------------------------------------
// tf32 tensor-core GEMM with cp.async double-buffered pipeline.
//   C[M x 256] = act(A[M x K] @ W[K x 256] + bias)[+res]
//   W comes from g_wt (pre-rounded tf32 bits) -> no cvt on B path.
//   A fragments cvt.rna'd in-register after SMEM load (exact RNA path).
// ---------------------------------------------------------------------------
template<int ACT>
__global__ void __launch_bounds__(256, 2) mma_gemm_k(
    int Aid, int wOff, const float* __restrict__ bias,
    int resId, int Cid, int K)
{
    __shared__ float As[2][128][20];   // 2 stages, 128 rows, 16 k + 4 pad
    __shared__ float Bs[2][16][132];   // 2 stages, 16 k, 128 n + 4 pad

    const float* __restrict__ A = bufsel(Aid);
    const float* __restrict__ W = g_wt + wOff;
    float* __restrict__ C = bufsel(Cid);

    const int tid  = threadIdx.x;
    const int bm   = blockIdx.x * 128;
    const int bn   = blockIdx.y * 128;
    const int w    = tid >> 5;
    const int lane = tid & 31;
    const int g    = lane >> 2;     // 0..7
    const int tq   = lane & 3;      // 0..3
    const int wm   = (w & 1) * 64;
    const int wn   = (w >> 1) * 32;

    // copy mapping: 4 x 16B cp.async per thread per tile
    const int ar  = tid & 127;       // A row
    const int ak0 = tid >> 7;        // 0..1 -> k-quads ak0, ak0+2
    const int bk0 = tid >> 5;        // 0..7 -> B k-rows bk0, bk0+8
    const int bq  = (tid & 31) * 4;  // B n offset

    const float* Ag  = A + (size_t)(bm + ar) * K;
    const float* Wg0 = W + (size_t)bk0 * DIM + bn + bq;
    const float* Wg1 = W + (size_t)(bk0 + 8) * DIM + bn + bq;

    unsigned dA0[2], dA1[2], dB0[2], dB1[2];
#pragma unroll
    for (int s = 0; s < 2; s++) {
        dA0[s] = (unsigned)__cvta_generic_to_shared(&As[s][ar][ak0 * 4]);
        dA1[s] = (unsigned)__cvta_generic_to_shared(&As[s][ar][(ak0 + 2) * 4]);
        dB0[s] = (unsigned)__cvta_generic_to_shared(&Bs[s][bk0][bq]);
        dB1[s] = (unsigned)__cvta_generic_to_shared(&Bs[s][bk0 + 8][bq]);
    }

    float acc[4][4][4];
#pragma unroll
    for (int mi = 0; mi < 4; mi++)
#pragma unroll
        for (int ni = 0; ni < 4; ni++)
#pragma unroll
            for (int r = 0; r < 4; r++) acc[mi][ni][r] = 0.f;

    // prologue: issue stage 0
    cp16(dA0[0], Ag + ak0 * 4);
    cp16(dA1[0], Ag + (ak0 + 2) * 4);
    cp16(dB0[0], Wg0);
    cp16(dB1[0], Wg1);
    asm volatile("cp.async.commit_group;" ::: "memory");

    const int niter = K / 16;
    for (int it = 0; it < niter; it++) {
        const int cur = it & 1;
        if (it + 1 < niter) {
            const int nxt = (it + 1) & 1;
            const int k0  = (it + 1) * 16;
            cp16(dA0[nxt], Ag + k0 + ak0 * 4);
            cp16(dA1[nxt], Ag + k0 + (ak0 + 2) * 4);
            cp16(dB0[nxt], Wg0 + (size_t)k0 * DIM);
            cp16(dB1[nxt], Wg1 + (size_t)k0 * DIM);
            asm volatile("cp.async.commit_group;" ::: "memory");
            asm volatile("cp.async.wait_group 1;" ::: "memory");
        } else {
            asm volatile("cp.async.wait_group 0;" ::: "memory");
        }
        __syncthreads();

#pragma unroll
        for (int kb2 = 0; kb2 < 2; kb2++) {
            const int kb = kb2 * 8;
            unsigned a[4][4], b[4][2];
#pragma unroll
            for (int mi = 0; mi < 4; mi++) {
                const int m0 = wm + mi * 16 + g;
                a[mi][0] = tf32r(As[cur][m0][kb + tq]);
                a[mi][1] = tf32r(As[cur][m0 + 8][kb + tq]);
                a[mi][2] = tf32r(As[cur][m0][kb + tq + 4]);
                a[mi][3] = tf32r(As[cur][m0 + 8][kb + tq + 4]);
            }
#pragma unroll
            for (int ni = 0; ni < 4; ni++) {
                const int n0 = wn + ni * 8 + g;
                b[ni][0] = __float_as_uint(Bs[cur][kb + tq][n0]);     // pre-rounded
                b[ni][1] = __float_as_uint(Bs[cur][kb + tq + 4][n0]); // pre-rounded
            }
#pragma unroll
            for (int mi = 0; mi < 4; mi++)
#pragma unroll
                for (int ni = 0; ni < 4; ni++)
                    mma_tf32(acc[mi][ni], a[mi], b[ni]);
        }
        __syncthreads();   // protect cur buffer before it is re-filled
    }

    const float* res = (resId >= 0) ? bufsel(resId) : nullptr;
#pragma unroll
    for (int mi = 0; mi < 4; mi++) {
#pragma unroll
        for (int h = 0; h < 2; h++) {
            const int row = bm + wm + mi * 16 + g + h * 8;
#pragma unroll
            for (int ni = 0; ni < 4; ni++) {
                const int c = bn + wn + ni * 8 + tq * 2;
                float v0 = acc[mi][ni][h * 2 + 0];
                float v1 = acc[mi][ni][h * 2 + 1];
                if (bias) {
                    float2 bb = *(const float2*)(bias + c);
                    v0 += bb.x; v1 += bb.y;
                }
                if (ACT == 1) { v0 = gelu_f(v0); v1 = gelu_f(v1); }
                const size_t off = (size_t)row * DIM + c;
                if (res) {
                    float2 r = *(const float2*)(res + off);
                    v0 += r.x; v1 += r.y;
                }
                float2 o; o.x = v0; o.y = v1;
                *(float2*)(C + off) = o;
            }
        }
    }
}

// ---------------------------------------------------------------------------
// scatter (proven): out[dst] += gelu(P[src] + Q[dst] + R[e])
// ---------------------------------------------------------------------------
__global__ void __launch_bounds__(256) scatter_k(
    const int* __restrict__ ei, int outId)
{
    float* __restrict__ out = bufsel(outId);
    int gt = blockIdx.x * 256 + threadIdx.x;
    int e  = gt >> 6;
    int c  = (gt & 63) * 4;
    int s = ei[e];
    int d = ei[NE + e];

    float4 p = *(const float4*)(g_P + (size_t)s * DIM + c);
    float4 q = *(const float4*)(g_Q + (size_t)d * DIM + c);
    float4 r = *(const float4*)(g_R + (size_t)e * DIM + c);
    float4 m;
    m.x = gelu_f(p.x + q.x + r.x);
    m.y = gelu_f(p.y + q.y + r.y);
    m.z = gelu_f(p.z + q.z + r.z);
    m.w = gelu_f(p.w + q.w + r.w);

    float* o = out + (size_t)d * DIM + c;
    asm volatile("red.global.add.v4.f32 [%0], {%1, %2, %3, %4};"
                 :: "l"(o), "f"(m.x), "f"(m.y), "f"(m.z), "f"(m.w)
                 : "memory");
}

// ---------------------------------------------------------------------------
extern "C" void kernel_launch(void* const* d_in, const int* in_sizes, int n_in,
                              void* d_out, int out_size)
{
    const float* x     = (const float*)d_in[0];
    const int*   ei    = (const int*)d_in[1];
    const float* attr  = (const float*)d_in[2];
    const float* ee_w1 = (const float*)d_in[3];
    const float* ee_b1 = (const float*)d_in[4];
    const float* ee_w2 = (const float*)d_in[5];
    const float* ee_b2 = (const float*)d_in[6];
    const float* ff1_w = (const float*)d_in[7];
    const float* ff1_b = (const float*)d_in[8];
    const float* mp1_w = (const float*)d_in[9];
    const float* mp1_b = (const float*)d_in[10];
    const float* mp2_w = (const float*)d_in[11];
    const float* mp2_b = (const float*)d_in[12];
    const float* ff2_w = (const float*)d_in[13];
    const float* ff2_b = (const float*)d_in[14];
    float* out = (float*)d_out;

    const int n4 = NN * DIM / 4;
    const int cb = (n4 + 255) / 256;
    const dim3 gN(NN / 128, 2);     // node GEMMs: M=49152
    const dim3 gE(NE / 128, 2);     // edge GEMM: M=393216

    // pre-round all weights into g_wt (tf32 RNA)
    cvtw_k<<<(262144/4 + 255)/256, 256>>>(ff1_w, WOFF_FF1/4, 262144/4);
    cvtw_k<<<(655360/4 + 255)/256, 256>>>(mp1_w, WOFF_MP1/4, 655360/4);
    cvtw_k<<<(655360/4 + 255)/256, 256>>>(mp2_w, WOFF_MP2/4, 655360/4);
    cvtw_k<<<(262144/4 + 255)/256, 256>>>(ff2_w, WOFF_FF2/4, 262144/4);

    copy_in_k<<<cb, 256>>>(x, B_X, n4);
    edge_embed_k<<<NE / 2, 256>>>(attr, ee_w1, ee_b1, ee_w2, ee_b2);

    for (int i = 0; i < DEPTH; i++) {
        const int f1o = WOFF_FF1 + i * DIM * DIM;
        const int f2o = WOFF_FF2 + i * DIM * DIM;
        const int m1o = WOFF_MP1 + i * 640 * DIM;
        const int m2o = WOFF_MP2 + i * 640 * DIM;

        // h = gelu(x @ ff1_w + ff1_b) -> hA
        mma_gemm_k<1><<<gN, 256>>>(B_X, f1o, ff1_b + i * DIM, -1, B_HA, DIM);

        // message pass 1: hA -> hB
        mma_gemm_k<0><<<gN, 256>>>(B_HA, m1o,             mp1_b + i * DIM, -1, B_P, DIM);
        mma_gemm_k<0><<<gN, 256>>>(B_HA, m1o + 256 * DIM, nullptr,         -1, B_Q, DIM);
        mma_gemm_k<0><<<gE, 256>>>(B_E,  m1o + 512 * DIM, nullptr,         -1, B_R, EEMB);
        copy_k<<<cb, 256>>>(B_HA, B_HB, n4);
        scatter_k<<<NE / 4, 256>>>(ei, B_HB);

        // message pass 2: hB -> hA
        mma_gemm_k<0><<<gN, 256>>>(B_HB, m2o,             mp2_b + i * DIM, -1, B_P, DIM);
        mma_gemm_k<0><<<gN, 256>>>(B_HB, m2o + 256 * DIM, nullptr,         -1, B_Q, DIM);
        mma_gemm_k<0><<<gE, 256>>>(B_E,  m2o + 512 * DIM, nullptr,         -1, B_R, EEMB);
        copy_k<<<cb, 256>>>(B_HB, B_HA, n4);
        scatter_k<<<NE / 4, 256>>>(ei, B_HA);

        // x = x + hA @ ff2_w + ff2_b
        mma_gemm_k<0><<<gN, 256>>>(B_HA, f2o, ff2_b + i * DIM, B_X, B_X, DIM);
    }

    copy_out_k<<<cb, 256>>>(B_X, out, n4);
}

// round 9
// speedup vs baseline: 2.0250x; 1.0969x over previous
#include <cuda_runtime.h>
#include <math.h>

#define NN 49152
#define NE 393216
#define DIM 256
#define EEMB 128
#define DEPTH 4

// ---- scratch (static device globals; no runtime allocation) ----
__device__ float g_e[(size_t)NE * EEMB];   // edge embeddings
__device__ float g_P[(size_t)NN * DIM];    // h @ Wa + b
__device__ float g_Q[(size_t)NN * DIM];    // h @ Wb
__device__ float g_hA[(size_t)NN * DIM];
__device__ float g_hB[(size_t)NN * DIM];
__device__ float g_x[(size_t)NN * DIM];
__device__ float g_wt[1835008];            // tf32-pre-rounded weights

// weight offsets inside g_wt (floats)
#define WOFF_FF1 0
#define WOFF_MP1 262144
#define WOFF_MP2 917504
#define WOFF_FF2 1572864

#define B_E  0
#define B_P  2
#define B_Q  3
#define B_HA 4
#define B_HB 5
#define B_X  6

__device__ __forceinline__ float* bufsel(int id) {
    switch (id) {
        case B_E:  return g_e;
        case B_P:  return g_P;
        case B_Q:  return g_Q;
        case B_HA: return g_hA;
        case B_HB: return g_hB;
        default:   return g_x;
    }
}

__device__ __forceinline__ float gelu_f(float v) {
    return 0.5f * v * (1.0f + erff(v * 0.70710678118654752440f));
}

__device__ __forceinline__ unsigned tf32r(float f) {
    unsigned u;
    asm("cvt.rna.tf32.f32 %0, %1;" : "=r"(u) : "f"(f));
    return u;
}

__device__ __forceinline__ void mma_tf32(float* c, const unsigned* a, const unsigned* b) {
    asm volatile(
        "mma.sync.aligned.m16n8k8.row.col.f32.tf32.tf32.f32 "
        "{%0,%1,%2,%3}, {%4,%5,%6,%7}, {%8,%9}, {%0,%1,%2,%3};\n"
        : "+f"(c[0]), "+f"(c[1]), "+f"(c[2]), "+f"(c[3])
        : "r"(a[0]), "r"(a[1]), "r"(a[2]), "r"(a[3]), "r"(b[0]), "r"(b[1]));
}

__device__ __forceinline__ void cp16(unsigned dst, const void* src) {
    asm volatile("cp.async.cg.shared.global [%0], [%1], 16;"
                 :: "r"(dst), "l"(src));
}

// ---------------------------------------------------------------------------
// weight pre-rounding
// ---------------------------------------------------------------------------
__global__ void cvtw_k(const float* __restrict__ src, int dstOff4, int n4) {
    int i = blockIdx.x * blockDim.x + threadIdx.x;
    if (i < n4) {
        float4 v = ((const float4*)src)[i];
        float4 o;
        o.x = __uint_as_float(tf32r(v.x));
        o.y = __uint_as_float(tf32r(v.y));
        o.z = __uint_as_float(tf32r(v.z));
        o.w = __uint_as_float(tf32r(v.w));
        ((float4*)g_wt)[dstOff4 + i] = o;
    }
}

// ---------------------------------------------------------------------------
// copies (proven)
// ---------------------------------------------------------------------------
__global__ void copy_k(int sid, int did, int n4) {
    int i = blockIdx.x * blockDim.x + threadIdx.x;
    if (i < n4) ((float4*)bufsel(did))[i] = ((const float4*)bufsel(sid))[i];
}
__global__ void copy_out_k(int sid, float* __restrict__ d, int n4) {
    int i = blockIdx.x * blockDim.x + threadIdx.x;
    if (i < n4) ((float4*)d)[i] = ((const float4*)bufsel(sid))[i];
}
__global__ void copy_in_k(const float* __restrict__ s, int did, int n4) {
    int i = blockIdx.x * blockDim.x + threadIdx.x;
    if (i < n4) ((float4*)bufsel(did))[i] = ((const float4*)s)[i];
}

// ---------------------------------------------------------------------------
// edge embedder (proven)
// ---------------------------------------------------------------------------
__global__ void __launch_bounds__(256) edge_embed_k(
    const float* __restrict__ attr,
    const float* __restrict__ w1, const float* __restrict__ b1,
    const float* __restrict__ w2, const float* __restrict__ b2)
{
    __shared__ float hid[2][EEMB];
    const int sub = threadIdx.x >> 7;
    const int j   = threadIdx.x & 127;
    const int e   = blockIdx.x * 2 + sub;

    float4 a = *(const float4*)(attr + (size_t)e * 4);
    float t = b1[j] + a.x * w1[j] + a.y * w1[EEMB + j]
                    + a.z * w1[2 * EEMB + j] + a.w * w1[3 * EEMB + j];
    hid[sub][j] = gelu_f(t);
    __syncthreads();

    float o0 = 0.f, o1 = 0.f, o2 = 0.f, o3 = 0.f;
#pragma unroll
    for (int k = 0; k < EEMB; k += 4) {
        o0 += hid[sub][k + 0] * __ldg(w2 + (k + 0) * EEMB + j);
        o1 += hid[sub][k + 1] * __ldg(w2 + (k + 1) * EEMB + j);
        o2 += hid[sub][k + 2] * __ldg(w2 + (k + 2) * EEMB + j);
        o3 += hid[sub][k + 3] * __ldg(w2 + (k + 3) * EEMB + j);
    }
    g_e[(size_t)e * EEMB + j] = b2[j] + ((o0 + o1) + (o2 + o3));
}

// ===========================================================================
// shared GEMM mainloop body (macro-free duplication kept minimal):
// Both kernels below use the identical cp.async double-buffered core from R8.
// ===========================================================================

// ---------------------------------------------------------------------------
// node GEMM (proven R8): C[M x 256] = act(A @ W + bias)[+res]
// ---------------------------------------------------------------------------
template<int ACT>
__global__ void __launch_bounds__(256, 2) mma_gemm_k(
    int Aid, int wOff, const float* __restrict__ bias,
    int resId, int Cid, int K)
{
    __shared__ float As[2][128][20];
    __shared__ float Bs[2][16][132];

    const float* __restrict__ A = bufsel(Aid);
    const float* __restrict__ W = g_wt + wOff;
    float* __restrict__ C = bufsel(Cid);

    const int tid  = threadIdx.x;
    const int bm   = blockIdx.x * 128;
    const int bn   = blockIdx.y * 128;
    const int w    = tid >> 5;
    const int lane = tid & 31;
    const int g    = lane >> 2;
    const int tq   = lane & 3;
    const int wm   = (w & 1) * 64;
    const int wn   = (w >> 1) * 32;

    const int ar  = tid & 127;
    const int ak0 = tid >> 7;
    const int bk0 = tid >> 5;
    const int bq  = (tid & 31) * 4;

    const float* Ag  = A + (size_t)(bm + ar) * K;
    const float* Wg0 = W + (size_t)bk0 * DIM + bn + bq;
    const float* Wg1 = W + (size_t)(bk0 + 8) * DIM + bn + bq;

    unsigned dA0[2], dA1[2], dB0[2], dB1[2];
#pragma unroll
    for (int s = 0; s < 2; s++) {
        dA0[s] = (unsigned)__cvta_generic_to_shared(&As[s][ar][ak0 * 4]);
        dA1[s] = (unsigned)__cvta_generic_to_shared(&As[s][ar][(ak0 + 2) * 4]);
        dB0[s] = (unsigned)__cvta_generic_to_shared(&Bs[s][bk0][bq]);
        dB1[s] = (unsigned)__cvta_generic_to_shared(&Bs[s][bk0 + 8][bq]);
    }

    float acc[4][4][4];
#pragma unroll
    for (int mi = 0; mi < 4; mi++)
#pragma unroll
        for (int ni = 0; ni < 4; ni++)
#pragma unroll
            for (int r = 0; r < 4; r++) acc[mi][ni][r] = 0.f;

    cp16(dA0[0], Ag + ak0 * 4);
    cp16(dA1[0], Ag + (ak0 + 2) * 4);
    cp16(dB0[0], Wg0);
    cp16(dB1[0], Wg1);
    asm volatile("cp.async.commit_group;" ::: "memory");

    const int niter = K / 16;
    for (int it = 0; it < niter; it++) {
        const int cur = it & 1;
        if (it + 1 < niter) {
            const int nxt = (it + 1) & 1;
            const int k0  = (it + 1) * 16;
            cp16(dA0[nxt], Ag + k0 + ak0 * 4);
            cp16(dA1[nxt], Ag + k0 + (ak0 + 2) * 4);
            cp16(dB0[nxt], Wg0 + (size_t)k0 * DIM);
            cp16(dB1[nxt], Wg1 + (size_t)k0 * DIM);
            asm volatile("cp.async.commit_group;" ::: "memory");
            asm volatile("cp.async.wait_group 1;" ::: "memory");
        } else {
            asm volatile("cp.async.wait_group 0;" ::: "memory");
        }
        __syncthreads();

#pragma unroll
        for (int kb2 = 0; kb2 < 2; kb2++) {
            const int kb = kb2 * 8;
            unsigned a[4][4], b[4][2];
#pragma unroll
            for (int mi = 0; mi < 4; mi++) {
                const int m0 = wm + mi * 16 + g;
                a[mi][0] = tf32r(As[cur][m0][kb + tq]);
                a[mi][1] = tf32r(As[cur][m0 + 8][kb + tq]);
                a[mi][2] = tf32r(As[cur][m0][kb + tq + 4]);
                a[mi][3] = tf32r(As[cur][m0 + 8][kb + tq + 4]);
            }
#pragma unroll
            for (int ni = 0; ni < 4; ni++) {
                const int n0 = wn + ni * 8 + g;
                b[ni][0] = __float_as_uint(Bs[cur][kb + tq][n0]);
                b[ni][1] = __float_as_uint(Bs[cur][kb + tq + 4][n0]);
            }
#pragma unroll
            for (int mi = 0; mi < 4; mi++)
#pragma unroll
                for (int ni = 0; ni < 4; ni++)
                    mma_tf32(acc[mi][ni], a[mi], b[ni]);
        }
        __syncthreads();
    }

    const float* res = (resId >= 0) ? bufsel(resId) : nullptr;
#pragma unroll
    for (int mi = 0; mi < 4; mi++) {
#pragma unroll
        for (int h = 0; h < 2; h++) {
            const int row = bm + wm + mi * 16 + g + h * 8;
#pragma unroll
            for (int ni = 0; ni < 4; ni++) {
                const int c = bn + wn + ni * 8 + tq * 2;
                float v0 = acc[mi][ni][h * 2 + 0];
                float v1 = acc[mi][ni][h * 2 + 1];
                if (bias) {
                    float2 bb = *(const float2*)(bias + c);
                    v0 += bb.x; v1 += bb.y;
                }
                if (ACT == 1) { v0 = gelu_f(v0); v1 = gelu_f(v1); }
                const size_t off = (size_t)row * DIM + c;
                if (res) {
                    float2 r = *(const float2*)(res + off);
                    v0 += r.x; v1 += r.y;
                }
                float2 o; o.x = v0; o.y = v1;
                *(float2*)(C + off) = o;
            }
        }
    }
}

// ---------------------------------------------------------------------------
// FUSED edge GEMM + scatter.  K = EEMB = 128 (fixed).
//   acc = e[bm..bm+127] @ Wc ;  per row: m = gelu(acc + P[src] + Q[dst]);
//   red.global.add.v4.f32 into C[dst].
//   Butterfly shuffle (lane^1) merges adjacent n-groups -> 4 consecutive cols
//   per lane, enabling the proven v4 reduction.
// ---------------------------------------------------------------------------
__global__ void __launch_bounds__(256, 2) mma_edge_k(
    int wOff, const int* __restrict__ ei, int Cid)
{
    __shared__ float As[2][128][20];
    __shared__ float Bs[2][16][132];
    __shared__ int sSrc[128], sDst[128];

    const float* __restrict__ A = g_e;
    const float* __restrict__ W = g_wt + wOff;
    float* __restrict__ C = bufsel(Cid);

    const int tid  = threadIdx.x;
    const int bm   = blockIdx.x * 128;
    const int bn   = blockIdx.y * 128;
    const int w    = tid >> 5;
    const int lane = tid & 31;
    const int g    = lane >> 2;
    const int tq   = lane & 3;
    const int wm   = (w & 1) * 64;
    const int wn   = (w >> 1) * 32;

    if (tid < 128) {
        sSrc[tid] = ei[bm + tid];
        sDst[tid] = ei[NE + bm + tid];
    }

    const int ar  = tid & 127;
    const int ak0 = tid >> 7;
    const int bk0 = tid >> 5;
    const int bq  = (tid & 31) * 4;

    const float* Ag  = A + (size_t)(bm + ar) * EEMB;
    const float* Wg0 = W + (size_t)bk0 * DIM + bn + bq;
    const float* Wg1 = W + (size_t)(bk0 + 8) * DIM + bn + bq;

    unsigned dA0[2], dA1[2], dB0[2], dB1[2];
#pragma unroll
    for (int s = 0; s < 2; s++) {
        dA0[s] = (unsigned)__cvta_generic_to_shared(&As[s][ar][ak0 * 4]);
        dA1[s] = (unsigned)__cvta_generic_to_shared(&As[s][ar][(ak0 + 2) * 4]);
        dB0[s] = (unsigned)__cvta_generic_to_shared(&Bs[s][bk0][bq]);
        dB1[s] = (unsigned)__cvta_generic_to_shared(&Bs[s][bk0 + 8][bq]);
    }

    float acc[4][4][4];
#pragma unroll
    for (int mi = 0; mi < 4; mi++)
#pragma unroll
        for (int ni = 0; ni < 4; ni++)
#pragma unroll
            for (int r = 0; r < 4; r++) acc[mi][ni][r] = 0.f;

    cp16(dA0[0], Ag + ak0 * 4);
    cp16(dA1[0], Ag + (ak0 + 2) * 4);
    cp16(dB0[0], Wg0);
    cp16(dB1[0], Wg1);
    asm volatile("cp.async.commit_group;" ::: "memory");

    const int niter = EEMB / 16;   // 8
    for (int it = 0; it < niter; it++) {
        const int cur = it & 1;
        if (it + 1 < niter) {
            const int nxt = (it + 1) & 1;
            const int k0  = (it + 1) * 16;
            cp16(dA0[nxt], Ag + k0 + ak0 * 4);
            cp16(dA1[nxt], Ag + k0 + (ak0 + 2) * 4);
            cp16(dB0[nxt], Wg0 + (size_t)k0 * DIM);
            cp16(dB1[nxt], Wg1 + (size_t)k0 * DIM);
            asm volatile("cp.async.commit_group;" ::: "memory");
            asm volatile("cp.async.wait_group 1;" ::: "memory");
        } else {
            asm volatile("cp.async.wait_group 0;" ::: "memory");
        }
        __syncthreads();

#pragma unroll
        for (int kb2 = 0; kb2 < 2; kb2++) {
            const int kb = kb2 * 8;
            unsigned a[4][4], b[4][2];
#pragma unroll
            for (int mi = 0; mi < 4; mi++) {
                const int m0 = wm + mi * 16 + g;
                a[mi][0] = tf32r(As[cur][m0][kb + tq]);
                a[mi][1] = tf32r(As[cur][m0 + 8][kb + tq]);
                a[mi][2] = tf32r(As[cur][m0][kb + tq + 4]);
                a[mi][3] = tf32r(As[cur][m0 + 8][kb + tq + 4]);
            }
#pragma unroll
            for (int ni = 0; ni < 4; ni++) {
                const int n0 = wn + ni * 8 + g;
                b[ni][0] = __float_as_uint(Bs[cur][kb + tq][n0]);
                b[ni][1] = __float_as_uint(Bs[cur][kb + tq + 4][n0]);
            }
#pragma unroll
            for (int mi = 0; mi < 4; mi++)
#pragma unroll
                for (int ni = 0; ni < 4; ni++)
                    mma_tf32(acc[mi][ni], a[mi], b[ni]);
        }
        __syncthreads();   // also orders sSrc/sDst before epilogue reads
    }

    // fused scatter epilogue (v4 reductions via lane^1 butterfly)
    const bool odd = (tq & 1);
#pragma unroll
    for (int mi = 0; mi < 4; mi++) {
#pragma unroll
        for (int h = 0; h < 2; h++) {
            const int lr = wm + mi * 16 + g + h * 8;
            const int s = sSrc[lr];
            const int d = sDst[lr];
            const float* Pp = g_P + (size_t)s * DIM;
            const float* Qp = g_Q + (size_t)d * DIM;
            float* Op = C + (size_t)d * DIM;
#pragma unroll
            for (int p = 0; p < 2; p++) {
                // send partner the half it needs; keep own half
                float s0 = odd ? acc[mi][2*p][h*2+0] : acc[mi][2*p+1][h*2+0];
                float s1 = odd ? acc[mi][2*p][h*2+1] : acc[mi][2*p+1][h*2+1];
                float r0 = __shfl_xor_sync(0xffffffffu, s0, 1);
                float r1 = __shfl_xor_sync(0xffffffffu, s1, 1);
                float o0 = odd ? acc[mi][2*p+1][h*2+0] : acc[mi][2*p][h*2+0];
                float o1 = odd ? acc[mi][2*p+1][h*2+1] : acc[mi][2*p][h*2+1];
                float4 v;
                if (odd) { v.x = r0; v.y = r1; v.z = o0; v.w = o1; }
                else     { v.x = o0; v.y = o1; v.z = r0; v.w = r1; }

                const int c = bn + wn + p * 16 + (tq & 1) * 8 + (tq >> 1) * 4;
                float4 pv = *(const float4*)(Pp + c);
                float4 qv = *(const float4*)(Qp + c);
                v.x = gelu_f(v.x + pv.x + qv.x);
                v.y = gelu_f(v.y + pv.y + qv.y);
                v.z = gelu_f(v.z + pv.z + qv.z);
                v.w = gelu_f(v.w + pv.w + qv.w);

                asm volatile("red.global.add.v4.f32 [%0], {%1, %2, %3, %4};"
                             :: "l"(Op + c), "f"(v.x), "f"(v.y), "f"(v.z), "f"(v.w)
                             : "memory");
            }
        }
    }
}

// ---------------------------------------------------------------------------
extern "C" void kernel_launch(void* const* d_in, const int* in_sizes, int n_in,
                              void* d_out, int out_size)
{
    const float* x     = (const float*)d_in[0];
    const int*   ei    = (const int*)d_in[1];
    const float* attr  = (const float*)d_in[2];
    const float* ee_w1 = (const float*)d_in[3];
    const float* ee_b1 = (const float*)d_in[4];
    const float* ee_w2 = (const float*)d_in[5];
    const float* ee_b2 = (const float*)d_in[6];
    const float* ff1_w = (const float*)d_in[7];
    const float* ff1_b = (const float*)d_in[8];
    const float* mp1_w = (const float*)d_in[9];
    const float* mp1_b = (const float*)d_in[10];
    const float* mp2_w = (const float*)d_in[11];
    const float* mp2_b = (const float*)d_in[12];
    const float* ff2_w = (const float*)d_in[13];
    const float* ff2_b = (const float*)d_in[14];
    float* out = (float*)d_out;

    const int n4 = NN * DIM / 4;
    const int cb = (n4 + 255) / 256;
    const dim3 gN(NN / 128, 2);     // node GEMMs
    const dim3 gE(NE / 128, 2);     // fused edge GEMM+scatter

    // pre-round all weights into g_wt (tf32 RNA)
    cvtw_k<<<(262144/4 + 255)/256, 256>>>(ff1_w, WOFF_FF1/4, 262144/4);
    cvtw_k<<<(655360/4 + 255)/256, 256>>>(mp1_w, WOFF_MP1/4, 655360/4);
    cvtw_k<<<(655360/4 + 255)/256, 256>>>(mp2_w, WOFF_MP2/4, 655360/4);
    cvtw_k<<<(262144/4 + 255)/256, 256>>>(ff2_w, WOFF_FF2/4, 262144/4);

    copy_in_k<<<cb, 256>>>(x, B_X, n4);
    edge_embed_k<<<NE / 2, 256>>>(attr, ee_w1, ee_b1, ee_w2, ee_b2);

    for (int i = 0; i < DEPTH; i++) {
        const int f1o = WOFF_FF1 + i * DIM * DIM;
        const int f2o = WOFF_FF2 + i * DIM * DIM;
        const int m1o = WOFF_MP1 + i * 640 * DIM;
        const int m2o = WOFF_MP2 + i * 640 * DIM;

        // h = gelu(x @ ff1_w + ff1_b) -> hA
        mma_gemm_k<1><<<gN, 256>>>(B_X, f1o, ff1_b + i * DIM, -1, B_HA, DIM);

        // message pass 1: hA -> hB
        mma_gemm_k<0><<<gN, 256>>>(B_HA, m1o,             mp1_b + i * DIM, -1, B_P, DIM);
        mma_gemm_k<0><<<gN, 256>>>(B_HA, m1o + 256 * DIM, nullptr,         -1, B_Q, DIM);
        copy_k<<<cb, 256>>>(B_HA, B_HB, n4);
        mma_edge_k<<<gE, 256>>>(m1o + 512 * DIM, ei, B_HB);

        // message pass 2: hB -> hA
        mma_gemm_k<0><<<gN, 256>>>(B_HB, m2o,             mp2_b + i * DIM, -1, B_P, DIM);
        mma_gemm_k<0><<<gN, 256>>>(B_HB, m2o + 256 * DIM, nullptr,         -1, B_Q, DIM);
        copy_k<<<cb, 256>>>(B_HB, B_HA, n4);
        mma_edge_k<<<gE, 256>>>(m2o + 512 * DIM, ei, B_HA);

        // x = x + hA @ ff2_w + ff2_b
        mma_gemm_k<0><<<gN, 256>>>(B_HA, f2o, ff2_b + i * DIM, B_X, B_X, DIM);
    }

    copy_out_k<<<cb, 256>>>(B_X, out, n4);
}

// round 10
// speedup vs baseline: 2.3812x; 1.1759x over previous
#include <cuda_runtime.h>
#include <math.h>

#define NN 49152
#define NE 393216
#define DIM 256
#define EEMB 128
#define DEPTH 4

// ---- scratch (static device globals; no runtime allocation) ----
__device__ float g_e[(size_t)NE * EEMB];     // edge embeddings
__device__ float g_hid[(size_t)NE * EEMB];   // edge-embed hidden layer
__device__ float g_P[(size_t)NN * DIM];      // h @ Wa + b
__device__ float g_Q[(size_t)NN * DIM];      // h @ Wb
__device__ float g_hA[(size_t)NN * DIM];
__device__ float g_hB[(size_t)NN * DIM];
__device__ float g_x[(size_t)NN * DIM];
__device__ float g_wt[1851392];              // tf32-pre-rounded weights

// weight offsets inside g_wt (floats)
#define WOFF_FF1  0
#define WOFF_MP1  262144
#define WOFF_MP2  917504
#define WOFF_FF2  1572864
#define WOFF_EEW2 1835008

#define B_E   0
#define B_P   2
#define B_Q   3
#define B_HA  4
#define B_HB  5
#define B_X   6
#define B_HID 7

__device__ __forceinline__ float* bufsel(int id) {
    switch (id) {
        case B_E:   return g_e;
        case B_P:   return g_P;
        case B_Q:   return g_Q;
        case B_HA:  return g_hA;
        case B_HB:  return g_hB;
        case B_HID: return g_hid;
        default:    return g_x;
    }
}

__device__ __forceinline__ float gelu_f(float v) {
    return 0.5f * v * (1.0f + erff(v * 0.70710678118654752440f));
}

__device__ __forceinline__ unsigned tf32r(float f) {
    unsigned u;
    asm("cvt.rna.tf32.f32 %0, %1;" : "=r"(u) : "f"(f));
    return u;
}

__device__ __forceinline__ void mma_tf32(float* c, const unsigned* a, const unsigned* b) {
    asm volatile(
        "mma.sync.aligned.m16n8k8.row.col.f32.tf32.tf32.f32 "
        "{%0,%1,%2,%3}, {%4,%5,%6,%7}, {%8,%9}, {%0,%1,%2,%3};\n"
        : "+f"(c[0]), "+f"(c[1]), "+f"(c[2]), "+f"(c[3])
        : "r"(a[0]), "r"(a[1]), "r"(a[2]), "r"(a[3]), "r"(b[0]), "r"(b[1]));
}

__device__ __forceinline__ void cp16(unsigned dst, const void* src) {
    asm volatile("cp.async.cg.shared.global [%0], [%1], 16;"
                 :: "r"(dst), "l"(src));
}

// ---------------------------------------------------------------------------
// weight pre-rounding
// ---------------------------------------------------------------------------
__global__ void cvtw_k(const float* __restrict__ src, int dstOff4, int n4) {
    int i = blockIdx.x * blockDim.x + threadIdx.x;
    if (i < n4) {
        float4 v = ((const float4*)src)[i];
        float4 o;
        o.x = __uint_as_float(tf32r(v.x));
        o.y = __uint_as_float(tf32r(v.y));
        o.z = __uint_as_float(tf32r(v.z));
        o.w = __uint_as_float(tf32r(v.w));
        ((float4*)g_wt)[dstOff4 + i] = o;
    }
}

// ---------------------------------------------------------------------------
// input copy
// ---------------------------------------------------------------------------
__global__ void copy_in_k(const float* __restrict__ s, int did, int n4) {
    int i = blockIdx.x * blockDim.x + threadIdx.x;
    if (i < n4) ((float4*)bufsel(did))[i] = ((const float4*)s)[i];
}

// ---------------------------------------------------------------------------
// edge embedder layer 1: g_hid = gelu(attr @ w1 + b1)
// ---------------------------------------------------------------------------
__global__ void __launch_bounds__(256) ee1_k(
    const float* __restrict__ attr,
    const float* __restrict__ w1, const float* __restrict__ b1)
{
    const int sub = threadIdx.x >> 7;
    const int j   = threadIdx.x & 127;
    const int e   = blockIdx.x * 2 + sub;

    float4 a = *(const float4*)(attr + (size_t)e * 4);
    float t = b1[j] + a.x * __ldg(w1 + j) + a.y * __ldg(w1 + EEMB + j)
                    + a.z * __ldg(w1 + 2 * EEMB + j) + a.w * __ldg(w1 + 3 * EEMB + j);
    g_hid[(size_t)e * EEMB + j] = gelu_f(t);
}

// ---------------------------------------------------------------------------
// tf32 tensor-core GEMM (cp.async double-buffered, proven core).
//   C[M x N] = act(A[M x K] @ W[K x N] + bias)[+res]
//   ldW/ldC generalize N=128 (edge-embed) vs 256 (node) cases.
//   dupId >= 0: epilogue also copies A[row][c] -> dup[row][c]  (K == ldC)
//   Cext != nullptr overrides Cid (final output to d_out).
// ---------------------------------------------------------------------------
template<int ACT>
__global__ void __launch_bounds__(256, 2) mma_gemm_k(
    int Aid, int wOff, const float* __restrict__ bias,
    int resId, int dupId, int Cid, float* __restrict__ Cext,
    int K, int ldW, int ldC)
{
    __shared__ float As[2][128][20];
    __shared__ float Bs[2][16][136];   // 136: bank-conflict-free frag loads

    const float* __restrict__ A = bufsel(Aid);
    const float* __restrict__ W = g_wt + wOff;
    float* __restrict__ C = Cext ? Cext : bufsel(Cid);

    const int tid  = threadIdx.x;
    const int bm   = blockIdx.x * 128;
    const int bn   = blockIdx.y * 128;
    const int w    = tid >> 5;
    const int lane = tid & 31;
    const int g    = lane >> 2;
    const int tq   = lane & 3;
    const int wm   = (w & 1) * 64;
    const int wn   = (w >> 1) * 32;

    const int ar  = tid & 127;
    const int ak0 = tid >> 7;
    const int bk0 = tid >> 5;
    const int bq  = (tid & 31) * 4;

    const float* Ag  = A + (size_t)(bm + ar) * K;
    const float* Wg0 = W + (size_t)bk0 * ldW + bn + bq;
    const float* Wg1 = W + (size_t)(bk0 + 8) * ldW + bn + bq;

    unsigned dA0[2], dA1[2], dB0[2], dB1[2];
#pragma unroll
    for (int s = 0; s < 2; s++) {
        dA0[s] = (unsigned)__cvta_generic_to_shared(&As[s][ar][ak0 * 4]);
        dA1[s] = (unsigned)__cvta_generic_to_shared(&As[s][ar][(ak0 + 2) * 4]);
        dB0[s] = (unsigned)__cvta_generic_to_shared(&Bs[s][bk0][bq]);
        dB1[s] = (unsigned)__cvta_generic_to_shared(&Bs[s][bk0 + 8][bq]);
    }

    float acc[4][4][4];
#pragma unroll
    for (int mi = 0; mi < 4; mi++)
#pragma unroll
        for (int ni = 0; ni < 4; ni++)
#pragma unroll
            for (int r = 0; r < 4; r++) acc[mi][ni][r] = 0.f;

    cp16(dA0[0], Ag + ak0 * 4);
    cp16(dA1[0], Ag + (ak0 + 2) * 4);
    cp16(dB0[0], Wg0);
    cp16(dB1[0], Wg1);
    asm volatile("cp.async.commit_group;" ::: "memory");

    const int niter = K / 16;
    for (int it = 0; it < niter; it++) {
        const int cur = it & 1;
        if (it + 1 < niter) {
            const int nxt = (it + 1) & 1;
            const int k0  = (it + 1) * 16;
            cp16(dA0[nxt], Ag + k0 + ak0 * 4);
            cp16(dA1[nxt], Ag + k0 + (ak0 + 2) * 4);
            cp16(dB0[nxt], Wg0 + (size_t)k0 * ldW);
            cp16(dB1[nxt], Wg1 + (size_t)k0 * ldW);
            asm volatile("cp.async.commit_group;" ::: "memory");
            asm volatile("cp.async.wait_group 1;" ::: "memory");
        } else {
            asm volatile("cp.async.wait_group 0;" ::: "memory");
        }
        __syncthreads();

#pragma unroll
        for (int kb2 = 0; kb2 < 2; kb2++) {
            const int kb = kb2 * 8;
            unsigned a[4][4], b[4][2];
#pragma unroll
            for (int mi = 0; mi < 4; mi++) {
                const int m0 = wm + mi * 16 + g;
                a[mi][0] = tf32r(As[cur][m0][kb + tq]);
                a[mi][1] = tf32r(As[cur][m0 + 8][kb + tq]);
                a[mi][2] = tf32r(As[cur][m0][kb + tq + 4]);
                a[mi][3] = tf32r(As[cur][m0 + 8][kb + tq + 4]);
            }
#pragma unroll
            for (int ni = 0; ni < 4; ni++) {
                const int n0 = wn + ni * 8 + g;
                b[ni][0] = __float_as_uint(Bs[cur][kb + tq][n0]);
                b[ni][1] = __float_as_uint(Bs[cur][kb + tq + 4][n0]);
            }
#pragma unroll
            for (int mi = 0; mi < 4; mi++)
#pragma unroll
                for (int ni = 0; ni < 4; ni++)
                    mma_tf32(acc[mi][ni], a[mi], b[ni]);
        }
        __syncthreads();
    }

    const float* res = (resId >= 0) ? bufsel(resId) : nullptr;
    float* dup = (dupId >= 0) ? bufsel(dupId) : nullptr;
#pragma unroll
    for (int mi = 0; mi < 4; mi++) {
#pragma unroll
        for (int h = 0; h < 2; h++) {
            const int row = bm + wm + mi * 16 + g + h * 8;
#pragma unroll
            for (int ni = 0; ni < 4; ni++) {
                const int c = bn + wn + ni * 8 + tq * 2;
                float v0 = acc[mi][ni][h * 2 + 0];
                float v1 = acc[mi][ni][h * 2 + 1];
                if (bias) {
                    float2 bb = *(const float2*)(bias + c);
                    v0 += bb.x; v1 += bb.y;
                }
                if (ACT == 1) { v0 = gelu_f(v0); v1 = gelu_f(v1); }
                const size_t off = (size_t)row * ldC + c;
                if (res) {
                    float2 r = *(const float2*)(res + off);
                    v0 += r.x; v1 += r.y;
                }
                if (dup) {   // copy A row slice (K == ldC layouts match)
                    const size_t offA = (size_t)row * K + c;
                    *(float2*)(dup + offA) = *(const float2*)(A + offA);
                }
                float2 o; o.x = v0; o.y = v1;
                *(float2*)(C + off) = o;
            }
        }
    }
}

// ---------------------------------------------------------------------------
// FUSED edge GEMM + scatter (proven R9; Bs padding fixed to 136).
// ---------------------------------------------------------------------------
__global__ void __launch_bounds__(256, 2) mma_edge_k(
    int wOff, const int* __restrict__ ei, int Cid)
{
    __shared__ float As[2][128][20];
    __shared__ float Bs[2][16][136];
    __shared__ int sSrc[128], sDst[128];

    const float* __restrict__ A = g_e;
    const float* __restrict__ W = g_wt + wOff;
    float* __restrict__ C = bufsel(Cid);

    const int tid  = threadIdx.x;
    const int bm   = blockIdx.x * 128;
    const int bn   = blockIdx.y * 128;
    const int w    = tid >> 5;
    const int lane = tid & 31;
    const int g    = lane >> 2;
    const int tq   = lane & 3;
    const int wm   = (w & 1) * 64;
    const int wn   = (w >> 1) * 32;

    if (tid < 128) {
        sSrc[tid] = ei[bm + tid];
        sDst[tid] = ei[NE + bm + tid];
    }

    const int ar  = tid & 127;
    const int ak0 = tid >> 7;
    const int bk0 = tid >> 5;
    const int bq  = (tid & 31) * 4;

    const float* Ag  = A + (size_t)(bm + ar) * EEMB;
    const float* Wg0 = W + (size_t)bk0 * DIM + bn + bq;
    const float* Wg1 = W + (size_t)(bk0 + 8) * DIM + bn + bq;

    unsigned dA0[2], dA1[2], dB0[2], dB1[2];
#pragma unroll
    for (int s = 0; s < 2; s++) {
        dA0[s] = (unsigned)__cvta_generic_to_shared(&As[s][ar][ak0 * 4]);
        dA1[s] = (unsigned)__cvta_generic_to_shared(&As[s][ar][(ak0 + 2) * 4]);
        dB0[s] = (unsigned)__cvta_generic_to_shared(&Bs[s][bk0][bq]);
        dB1[s] = (unsigned)__cvta_generic_to_shared(&Bs[s][bk0 + 8][bq]);
    }

    float acc[4][4][4];
#pragma unroll
    for (int mi = 0; mi < 4; mi++)
#pragma unroll
        for (int ni = 0; ni < 4; ni++)
#pragma unroll
            for (int r = 0; r < 4; r++) acc[mi][ni][r] = 0.f;

    cp16(dA0[0], Ag + ak0 * 4);
    cp16(dA1[0], Ag + (ak0 + 2) * 4);
    cp16(dB0[0], Wg0);
    cp16(dB1[0], Wg1);
    asm volatile("cp.async.commit_group;" ::: "memory");

    const int niter = EEMB / 16;   // 8
    for (int it = 0; it < niter; it++) {
        const int cur = it & 1;
        if (it + 1 < niter) {
            const int nxt = (it + 1) & 1;
            const int k0  = (it + 1) * 16;
            cp16(dA0[nxt], Ag + k0 + ak0 * 4);
            cp16(dA1[nxt], Ag + k0 + (ak0 + 2) * 4);
            cp16(dB0[nxt], Wg0 + (size_t)k0 * DIM);
            cp16(dB1[nxt], Wg1 + (size_t)k0 * DIM);
            asm volatile("cp.async.commit_group;" ::: "memory");
            asm volatile("cp.async.wait_group 1;" ::: "memory");
        } else {
            asm volatile("cp.async.wait_group 0;" ::: "memory");
        }
        __syncthreads();

#pragma unroll
        for (int kb2 = 0; kb2 < 2; kb2++) {
            const int kb = kb2 * 8;
            unsigned a[4][4], b[4][2];
#pragma unroll
            for (int mi = 0; mi < 4; mi++) {
                const int m0 = wm + mi * 16 + g;
                a[mi][0] = tf32r(As[cur][m0][kb + tq]);
                a[mi][1] = tf32r(As[cur][m0 + 8][kb + tq]);
                a[mi][2] = tf32r(As[cur][m0][kb + tq + 4]);
                a[mi][3] = tf32r(As[cur][m0 + 8][kb + tq + 4]);
            }
#pragma unroll
            for (int ni = 0; ni < 4; ni++) {
                const int n0 = wn + ni * 8 + g;
                b[ni][0] = __float_as_uint(Bs[cur][kb + tq][n0]);
                b[ni][1] = __float_as_uint(Bs[cur][kb + tq + 4][n0]);
            }
#pragma unroll
            for (int mi = 0; mi < 4; mi++)
#pragma unroll
                for (int ni = 0; ni < 4; ni++)
                    mma_tf32(acc[mi][ni], a[mi], b[ni]);
        }
        __syncthreads();
    }

    // fused scatter epilogue (v4 reductions via lane^1 butterfly)
    const bool odd = (tq & 1);
#pragma unroll
    for (int mi = 0; mi < 4; mi++) {
#pragma unroll
        for (int h = 0; h < 2; h++) {
            const int lr = wm + mi * 16 + g + h * 8;
            const int s = sSrc[lr];
            const int d = sDst[lr];
            const float* Pp = g_P + (size_t)s * DIM;
            const float* Qp = g_Q + (size_t)d * DIM;
            float* Op = C + (size_t)d * DIM;
#pragma unroll
            for (int p = 0; p < 2; p++) {
                float s0 = odd ? acc[mi][2*p][h*2+0] : acc[mi][2*p+1][h*2+0];
                float s1 = odd ? acc[mi][2*p][h*2+1] : acc[mi][2*p+1][h*2+1];
                float r0 = __shfl_xor_sync(0xffffffffu, s0, 1);
                float r1 = __shfl_xor_sync(0xffffffffu, s1, 1);
                float o0 = odd ? acc[mi][2*p+1][h*2+0] : acc[mi][2*p][h*2+0];
                float o1 = odd ? acc[mi][2*p+1][h*2+1] : acc[mi][2*p][h*2+1];
                float4 v;
                if (odd) { v.x = r0; v.y = r1; v.z = o0; v.w = o1; }
                else     { v.x = o0; v.y = o1; v.z = r0; v.w = r1; }

                const int c = bn + wn + p * 16 + (tq & 1) * 8 + (tq >> 1) * 4;
                float4 pv = *(const float4*)(Pp + c);
                float4 qv = *(const float4*)(Qp + c);
                v.x = gelu_f(v.x + pv.x + qv.x);
                v.y = gelu_f(v.y + pv.y + qv.y);
                v.z = gelu_f(v.z + pv.z + qv.z);
                v.w = gelu_f(v.w + pv.w + qv.w);

                asm volatile("red.global.add.v4.f32 [%0], {%1, %2, %3, %4};"
                             :: "l"(Op + c), "f"(v.x), "f"(v.y), "f"(v.z), "f"(v.w)
                             : "memory");
            }
        }
    }
}

// ---------------------------------------------------------------------------
extern "C" void kernel_launch(void* const* d_in, const int* in_sizes, int n_in,
                              void* d_out, int out_size)
{
    const float* x     = (const float*)d_in[0];
    const int*   ei    = (const int*)d_in[1];
    const float* attr  = (const float*)d_in[2];
    const float* ee_w1 = (const float*)d_in[3];
    const float* ee_b1 = (const float*)d_in[4];
    const float* ee_w2 = (const float*)d_in[5];
    const float* ee_b2 = (const float*)d_in[6];
    const float* ff1_w = (const float*)d_in[7];
    const float* ff1_b = (const float*)d_in[8];
    const float* mp1_w = (const float*)d_in[9];
    const float* mp1_b = (const float*)d_in[10];
    const float* mp2_w = (const float*)d_in[11];
    const float* mp2_b = (const float*)d_in[12];
    const float* ff2_w = (const float*)d_in[13];
    const float* ff2_b = (const float*)d_in[14];
    float* out = (float*)d_out;

    const int n4 = NN * DIM / 4;
    const int cb = (n4 + 255) / 256;
    const dim3 gN(NN / 128, 2);      // node GEMMs
    const dim3 gE(NE / 128, 2);      // fused edge GEMM+scatter
    const dim3 gEE(NE / 128, 1);     // edge-embed layer-2 GEMM (N=128)

    // pre-round all weights into g_wt (tf32 RNA)
    cvtw_k<<<(262144/4 + 255)/256, 256>>>(ff1_w, WOFF_FF1/4, 262144/4);
    cvtw_k<<<(655360/4 + 255)/256, 256>>>(mp1_w, WOFF_MP1/4, 655360/4);
    cvtw_k<<<(655360/4 + 255)/256, 256>>>(mp2_w, WOFF_MP2/4, 655360/4);
    cvtw_k<<<(262144/4 + 255)/256, 256>>>(ff2_w, WOFF_FF2/4, 262144/4);
    cvtw_k<<<(16384/4 + 255)/256, 256>>>(ee_w2, WOFF_EEW2/4, 16384/4);

    copy_in_k<<<cb, 256>>>(x, B_X, n4);

    // edge embedder: layer1 SIMT, layer2 tensor-core GEMM
    ee1_k<<<NE / 2, 256>>>(attr, ee_w1, ee_b1);
    mma_gemm_k<0><<<gEE, 256>>>(B_HID, WOFF_EEW2, ee_b2, -1, -1, B_E, nullptr,
                                EEMB, EEMB, EEMB);

    for (int i = 0; i < DEPTH; i++) {
        const int f1o = WOFF_FF1 + i * DIM * DIM;
        const int f2o = WOFF_FF2 + i * DIM * DIM;
        const int m1o = WOFF_MP1 + i * 640 * DIM;
        const int m2o = WOFF_MP2 + i * 640 * DIM;

        // h = gelu(x @ ff1_w + ff1_b) -> hA
        mma_gemm_k<1><<<gN, 256>>>(B_X, f1o, ff1_b + i * DIM, -1, -1, B_HA, nullptr,
                                   DIM, DIM, DIM);

        // message pass 1: hA -> hB
        mma_gemm_k<0><<<gN, 256>>>(B_HA, m1o,             mp1_b + i * DIM, -1, -1,  B_P, nullptr, DIM, DIM, DIM);
        mma_gemm_k<0><<<gN, 256>>>(B_HA, m1o + 256 * DIM, nullptr,         -1, B_HB, B_Q, nullptr, DIM, DIM, DIM);
        mma_edge_k<<<gE, 256>>>(m1o + 512 * DIM, ei, B_HB);

        // message pass 2: hB -> hA
        mma_gemm_k<0><<<gN, 256>>>(B_HB, m2o,             mp2_b + i * DIM, -1, -1,  B_P, nullptr, DIM, DIM, DIM);
        mma_gemm_k<0><<<gN, 256>>>(B_HB, m2o + 256 * DIM, nullptr,         -1, B_HA, B_Q, nullptr, DIM, DIM, DIM);
        mma_edge_k<<<gE, 256>>>(m2o + 512 * DIM, ei, B_HA);

        // x = x + hA @ ff2_w + ff2_b   (last layer writes d_out directly)
        mma_gemm_k<0><<<gN, 256>>>(B_HA, f2o, ff2_b + i * DIM, B_X, -1, B_X,
                                   (i == DEPTH - 1) ? out : nullptr, DIM, DIM, DIM);
    }
}